// round 1
// baseline (speedup 1.0000x reference)
#include <cuda_runtime.h>
#include <math.h>

#define F_DIM 257
#define T_DIM 257
#define NB 4
#define NPIX (F_DIM * T_DIM)        // 66049
#define NTOT (NB * NPIX)            // 264196
#define SLOPE 0.2f

// ---------------- scratch (no allocations allowed) ----------------
__device__ float d_h[NB * 2 * NPIX];          // STFT output (B,2,F,T)
__device__ float d_act0[NB * 64 * NPIX];      // ping
__device__ float d_act1[NB * 64 * NPIX];      // pong
__device__ float d_wh[14 * 7 * 64];           // conv1 weights, [ci][kw][o]
__device__ float d_wm[8 * 64 * 9 * 64];       // mid weights, [layer][(c*9+tap)*64+o]
__device__ float d_wl[578];                   // last conv [c*9+tap] + bias at [576]

// ---------------- weight-norm prep: normalize + transpose ----------------
__global__ void prep_kernel(const float* __restrict__ v_h, const float* __restrict__ g_h,
                            const float* __restrict__ vs,  const float* __restrict__ gs,
                            const float* __restrict__ v_last, const float* __restrict__ g_last,
                            const float* __restrict__ b_last) {
    __shared__ float red[128];
    int bid = blockIdx.x, tid = threadIdx.x;
    const float* base; int n; float g; int o = 0;
    if (bid < 64)        { o = bid; base = v_h + o * 98; n = 98; g = g_h[o]; }
    else if (bid < 576)  { int L = (bid - 64) >> 6; o = (bid - 64) & 63;
                           base = vs + (size_t)(L * 64 + o) * 576; n = 576; g = gs[L * 64 + o]; }
    else                 { base = v_last; n = 576; g = g_last[0]; }

    float s = 0.f;
    for (int i = tid; i < n; i += 128) { float v = base[i]; s += v * v; }
    red[tid] = s; __syncthreads();
    for (int k = 64; k > 0; k >>= 1) { if (tid < k) red[tid] += red[tid + k]; __syncthreads(); }
    float scale = g * rsqrtf(red[0]);

    if (bid < 64) {
        for (int i = tid; i < n; i += 128) d_wh[i * 64 + o] = base[i] * scale;
    } else if (bid < 576) {
        int L = (bid - 64) >> 6;
        for (int i = tid; i < n; i += 128) d_wm[(size_t)L * 36864 + i * 64 + o] = base[i] * scale;
    } else {
        for (int i = tid; i < n; i += 128) d_wl[i] = base[i] * scale;
        if (tid == 0) d_wl[576] = b_last[0];
    }
}

// ---------------- STFT: direct tabulated 512-pt rDFT ----------------
__global__ void stft_kernel(const float* __restrict__ x) {
    __shared__ float s[512], ct[512], st[512];
    int t = blockIdx.x, b = blockIdx.y, tid = threadIdx.x;
    const float* xb = x + (size_t)b * 65536;
    for (int n = tid; n < 512; n += 256) {
        int idx = t * 256 + n - 256;          // reflect padding, pad=256
        if (idx < 0) idx = -idx;
        if (idx >= 65536) idx = 131070 - idx;
        float w = 0.5f - 0.5f * cospif(n * (1.0f / 256.0f));   // Hann
        s[n] = xb[idx] * w;
        float ss, cc;
        sincospif(n * (1.0f / 256.0f), &ss, &cc);               // e^{-2πi m/512} tables
        ct[n] = cc; st[n] = ss;
    }
    __syncthreads();
    for (int f = tid; f < 257; f += 256) {
        float re = 0.f, im = 0.f;
        int m = 0;
        #pragma unroll 8
        for (int n = 0; n < 512; n++) {
            float v = s[n];
            re += v * ct[m];
            im -= v * st[m];
            m = (m + f) & 511;
        }
        d_h[((size_t)(b * 2 + 0) * F_DIM + f) * T_DIM + t] = re;
        d_h[((size_t)(b * 2 + 1) * F_DIM + f) * T_DIM + t] = im;
    }
}

// ---------------- fused lower + conv1(1x7) + bias + leaky ----------------
// Only lowered channels 10..13 are nonzero: k=5 (shift 154.1507) and k=6 (identity).
__global__ __launch_bounds__(256) void conv1_kernel(const float* __restrict__ b_h) {
    __shared__ float sw[1792];   // [ci4][kw][o], ci4 = ch-10
    __shared__ float sb[64];
    int tid = threadIdx.x;
    for (int i = tid; i < 1792; i += 256) sw[i] = d_wh[4480 + i];   // 10*7*64 = 4480
    if (tid < 64) sb[tid] = b_h[tid];
    __syncthreads();

    int pid = blockIdx.x * 256 + tid;
    if (pid >= NTOT) return;
    int b = pid / NPIX, rem = pid % NPIX;
    int f = rem / T_DIM, t = rem % T_DIM;

    const float shift5 = 154.15067982725832f;   // 1000*ln(7/6)
    float src  = (float)f - shift5;
    float lof  = floorf(src);
    float frac = src - lof;
    int   il   = (int)lof;
    const float* hb0 = d_h + ((size_t)(b * 2 + 0) * F_DIM) * T_DIM;
    const float* hb1 = d_h + ((size_t)(b * 2 + 1) * F_DIM) * T_DIM;

    float low[4][7];
    #pragma unroll
    for (int kw = 0; kw < 7; kw++) {
        int tt = t + kw - 3;
        bool tv = (tt >= 0) && (tt < T_DIM);
        float a0 = 0.f, a1 = 0.f, c0 = 0.f, c1 = 0.f, i0 = 0.f, i1 = 0.f;
        if (tv) {
            if (il >= 0 && il < F_DIM)          { a0 = hb0[il * T_DIM + tt];        a1 = hb1[il * T_DIM + tt]; }
            if (il + 1 >= 0 && il + 1 < F_DIM)  { c0 = hb0[(il + 1) * T_DIM + tt];  c1 = hb1[(il + 1) * T_DIM + tt]; }
            i0 = hb0[f * T_DIM + tt]; i1 = hb1[f * T_DIM + tt];
        }
        low[0][kw] = (1.0f - frac) * a0 + frac * c0;
        low[1][kw] = (1.0f - frac) * a1 + frac * c1;
        low[2][kw] = i0;
        low[3][kw] = i1;
    }

    float acc[64];
    #pragma unroll
    for (int o = 0; o < 64; o++) acc[o] = sb[o];
    #pragma unroll
    for (int ci = 0; ci < 4; ci++) {
        #pragma unroll
        for (int kw = 0; kw < 7; kw++) {
            float xv = low[ci][kw];
            const float* wp = &sw[(ci * 7 + kw) * 64];
            #pragma unroll
            for (int o = 0; o < 64; o++) acc[o] += xv * wp[o];
        }
    }
    float* out = d_act0 + (size_t)b * 64 * NPIX + rem;
    #pragma unroll
    for (int o = 0; o < 64; o++) {
        float y = acc[o];
        out[(size_t)o * NPIX] = (y > 0.f) ? y : SLOPE * y;
    }
}

// ---------------- dilated 3x3 conv 64->64 + bias + leaky ----------------
// Block: 32x8 threads; tile 32f x 32t x 16 oc; thread: 4 f-rows x 16 oc.
template <int D>
__global__ __launch_bounds__(256, 2) void conv3_kernel(int dir, int layer, const float* __restrict__ bs) {
    constexpr int TW = 32 + 2 * D;
    __shared__ float tile[TW * TW];
    __shared__ float wsm[144];

    const float* in  = dir ? d_act1 : d_act0;
    float*       out = dir ? d_act0 : d_act1;
    const float* wm  = d_wm + (size_t)layer * 36864;
    const float* bias = bs + layer * 64;

    int tx = threadIdx.x, ty = threadIdx.y;
    int tid = ty * 32 + tx;
    int bt = (blockIdx.x % 9) * 32, bf = (blockIdx.x / 9) * 32;
    int oc0 = blockIdx.y * 16;
    int b = blockIdx.z;

    float acc[4][16];
    #pragma unroll
    for (int i = 0; i < 4; i++)
        #pragma unroll
        for (int j = 0; j < 16; j++) acc[i][j] = 0.f;

    const float* inb = in + (size_t)b * 64 * NPIX;
    for (int c = 0; c < 64; c++) {
        const float* inc = inb + (size_t)c * NPIX;
        for (int i = tid; i < TW * TW; i += 256) {
            int r = i / TW, cc = i % TW;
            int gf = bf - D + r, gt = bt - D + cc;
            float v = 0.f;
            if (gf >= 0 && gf < F_DIM && gt >= 0 && gt < T_DIM) v = inc[gf * T_DIM + gt];
            tile[i] = v;
        }
        if (tid < 144) wsm[tid] = wm[(c * 9 + (tid >> 4)) * 64 + oc0 + (tid & 15)];
        __syncthreads();

        #pragma unroll
        for (int tap = 0; tap < 9; tap++) {
            const int kf = tap / 3, kt = tap % 3;
            float wv[16];
            #pragma unroll
            for (int j = 0; j < 16; j++) wv[j] = wsm[tap * 16 + j];
            #pragma unroll
            for (int fr = 0; fr < 4; fr++) {
                float xv = tile[(ty * 4 + fr + kf * D) * TW + tx + kt * D];
                #pragma unroll
                for (int j = 0; j < 16; j++) acc[fr][j] += xv * wv[j];
            }
        }
        __syncthreads();
    }

    int t = bt + tx;
    if (t < T_DIM) {
        #pragma unroll
        for (int fr = 0; fr < 4; fr++) {
            int f = bf + ty * 4 + fr;
            if (f < F_DIM) {
                #pragma unroll
                for (int j = 0; j < 16; j++) {
                    float y = acc[fr][j] + bias[oc0 + j];
                    y = (y > 0.f) ? y : SLOPE * y;
                    out[((size_t)(b * 64 + oc0 + j) * F_DIM + f) * T_DIM + t] = y;
                }
            }
        }
    }
}

// ---------------- last conv (64 -> 1, 3x3, pad 1), no activation ----------------
__global__ __launch_bounds__(256) void last_kernel(float* __restrict__ out) {
    __shared__ float sw[577];
    int tid = threadIdx.x;
    for (int i = tid; i < 577; i += 256) sw[i] = d_wl[i];
    __syncthreads();

    int pid = blockIdx.x * 256 + tid;
    if (pid >= NTOT) return;
    int b = pid / NPIX, rem = pid % NPIX;
    int f = rem / T_DIM, t = rem % T_DIM;
    const float* inb = d_act0 + (size_t)b * 64 * NPIX;

    float acc = sw[576];
    #pragma unroll
    for (int kf = 0; kf < 3; kf++) {
        int fi = f + kf - 1;
        if (fi < 0 || fi >= F_DIM) continue;
        #pragma unroll
        for (int kt = 0; kt < 3; kt++) {
            int ti = t + kt - 1;
            if (ti < 0 || ti >= T_DIM) continue;
            const float* p = inb + fi * T_DIM + ti;
            int wi = kf * 3 + kt;
            for (int c = 0; c < 64; c++)
                acc += __ldg(p + (size_t)c * NPIX) * sw[c * 9 + wi];
        }
    }
    out[pid] = acc;
}

// ---------------- launch ----------------
extern "C" void kernel_launch(void* const* d_in, const int* in_sizes, int n_in,
                              void* d_out, int out_size) {
    const float* x      = (const float*)d_in[0];
    const float* v_h    = (const float*)d_in[1];
    const float* g_h    = (const float*)d_in[2];
    const float* b_h    = (const float*)d_in[3];
    const float* vs     = (const float*)d_in[4];
    const float* gs     = (const float*)d_in[5];
    const float* bs     = (const float*)d_in[6];
    const float* v_last = (const float*)d_in[7];
    const float* g_last = (const float*)d_in[8];
    const float* b_last = (const float*)d_in[9];
    float* out = (float*)d_out;

    prep_kernel<<<577, 128>>>(v_h, g_h, vs, gs, v_last, g_last, b_last);
    stft_kernel<<<dim3(257, NB), 256>>>(x);
    conv1_kernel<<<(NTOT + 255) / 256, 256>>>(b_h);

    dim3 cg(81, 4, NB), cb(32, 8);
    conv3_kernel<1><<<cg, cb>>>(0, 0, bs);
    conv3_kernel<2><<<cg, cb>>>(1, 1, bs);
    conv3_kernel<3><<<cg, cb>>>(0, 2, bs);
    conv3_kernel<4><<<cg, cb>>>(1, 3, bs);
    conv3_kernel<5><<<cg, cb>>>(0, 4, bs);
    conv3_kernel<6><<<cg, cb>>>(1, 5, bs);
    conv3_kernel<7><<<cg, cb>>>(0, 6, bs);
    conv3_kernel<8><<<cg, cb>>>(1, 7, bs);

    last_kernel<<<(NTOT + 255) / 256, 256>>>(out);
}

// round 3
// speedup vs baseline: 3.1404x; 3.1404x over previous
#include <cuda_runtime.h>
#include <cuda_bf16.h>
#include <stdint.h>
#include <math.h>

#define F_DIM 257
#define T_DIM 257
#define NB 4
#define NPIX (F_DIM * T_DIM)        // 66049
#define NTOT (NB * NPIX)            // 264196
#define SLOPE 0.2f

// ======================= scratch =======================
__device__ float d_h[NB * 2 * NPIX];                                // STFT (B,2,F,T)
__device__ __align__(16) unsigned short d_a0h[(size_t)NTOT * 64];   // NHWC bf16 hi
__device__ __align__(16) unsigned short d_a0l[(size_t)NTOT * 64];   // NHWC bf16 lo
__device__ __align__(16) unsigned short d_a1h[(size_t)NTOT * 64];
__device__ __align__(16) unsigned short d_a1l[(size_t)NTOT * 64];
__device__ float d_wh[14 * 7 * 64];                                 // conv1 fp32 [ci][kw][o]
__device__ float d_wm[8 * 64 * 9 * 64];                             // mid fp32 [L][(c*9+tap)*64+o]
__device__ uint32_t d_wfh[8 * 9 * 4 * 8 * 2 * 32];                  // B frags hi [L][tap][ks][n8][reg][lane]
__device__ uint32_t d_wfl[8 * 9 * 4 * 8 * 2 * 32];                  // B frags lo
__device__ float d_wl[578];                                         // last conv fp32

// ======================= weight-norm prep =======================
__global__ void prep_kernel(const float* __restrict__ v_h, const float* __restrict__ g_h,
                            const float* __restrict__ vs,  const float* __restrict__ gs,
                            const float* __restrict__ v_last, const float* __restrict__ g_last,
                            const float* __restrict__ b_last) {
    __shared__ float red[128];
    int bid = blockIdx.x, tid = threadIdx.x;
    const float* base; int n; float g; int o = 0;
    if (bid < 64)        { o = bid; base = v_h + o * 98; n = 98; g = g_h[o]; }
    else if (bid < 576)  { int L = (bid - 64) >> 6; o = (bid - 64) & 63;
                           base = vs + (size_t)(L * 64 + o) * 576; n = 576; g = gs[L * 64 + o]; }
    else                 { base = v_last; n = 576; g = g_last[0]; }

    float s = 0.f;
    for (int i = tid; i < n; i += 128) { float v = base[i]; s += v * v; }
    red[tid] = s; __syncthreads();
    for (int k = 64; k > 0; k >>= 1) { if (tid < k) red[tid] += red[tid + k]; __syncthreads(); }
    float scale = g * rsqrtf(red[0]);

    if (bid < 64) {
        for (int i = tid; i < n; i += 128) d_wh[i * 64 + o] = base[i] * scale;
    } else if (bid < 576) {
        int L = (bid - 64) >> 6;
        for (int i = tid; i < n; i += 128) d_wm[(size_t)L * 36864 + i * 64 + o] = base[i] * scale;
    } else {
        for (int i = tid; i < n; i += 128) d_wl[i] = base[i] * scale;
        if (tid == 0) d_wl[576] = b_last[0];
    }
}

// ======================= build B fragments in mma lane layout =======================
// B frag (m16n8k16 col): lane holds k pair (ks*16 + reg*8 + (lane%4)*2, +1) for n = n8*8 + lane/4.
__global__ void wfrag_kernel() {
    int L = blockIdx.x, tap = blockIdx.y;
    const float* wm = d_wm + (size_t)L * 36864;
    for (int e = threadIdx.x; e < 2048; e += 256) {
        int lane = e & 31, reg = (e >> 5) & 1, n8 = (e >> 6) & 7, ks = (e >> 9) & 3;
        int k0 = ks * 16 + reg * 8 + (lane & 3) * 2;
        int nn = n8 * 8 + (lane >> 2);
        float w0 = wm[(k0 * 9 + tap) * 64 + nn];
        float w1 = wm[((k0 + 1) * 9 + tap) * 64 + nn];
        __nv_bfloat16 h0 = __float2bfloat16(w0), h1 = __float2bfloat16(w1);
        __nv_bfloat16 l0 = __float2bfloat16(w0 - __bfloat162float(h0));
        __nv_bfloat16 l1 = __float2bfloat16(w1 - __bfloat162float(h1));
        size_t idx = ((((size_t)(L * 9 + tap) * 4 + ks) * 8 + n8) * 2 + reg) * 32 + lane;
        d_wfh[idx] = ((uint32_t)__bfloat16_as_ushort(h1) << 16) | __bfloat16_as_ushort(h0);
        d_wfl[idx] = ((uint32_t)__bfloat16_as_ushort(l1) << 16) | __bfloat16_as_ushort(l0);
    }
}

// ======================= STFT =======================
__global__ void stft_kernel(const float* __restrict__ x) {
    __shared__ float s[512], ct[512], st[512];
    int t = blockIdx.x, b = blockIdx.y, tid = threadIdx.x;
    const float* xb = x + (size_t)b * 65536;
    for (int n = tid; n < 512; n += 256) {
        int idx = t * 256 + n - 256;
        if (idx < 0) idx = -idx;
        if (idx >= 65536) idx = 131070 - idx;
        float w = 0.5f - 0.5f * cospif(n * (1.0f / 256.0f));
        s[n] = xb[idx] * w;
        float ss, cc;
        sincospif(n * (1.0f / 256.0f), &ss, &cc);
        ct[n] = cc; st[n] = ss;
    }
    __syncthreads();
    for (int f = tid; f < 257; f += 256) {
        float re = 0.f, im = 0.f;
        int m = 0;
        #pragma unroll 8
        for (int n = 0; n < 512; n++) {
            float v = s[n];
            re += v * ct[m];
            im -= v * st[m];
            m = (m + f) & 511;
        }
        d_h[((size_t)(b * 2 + 0) * F_DIM + f) * T_DIM + t] = re;
        d_h[((size_t)(b * 2 + 1) * F_DIM + f) * T_DIM + t] = im;
    }
}

__device__ __forceinline__ uint32_t pack_bf2(float a, float b) {
    __nv_bfloat162 h = __floats2bfloat162_rn(a, b);
    return *reinterpret_cast<uint32_t*>(&h);
}

// ======================= fused lower + conv1 + leaky -> NHWC bf16 hi/lo =======================
__global__ __launch_bounds__(256) void conv1_kernel(const float* __restrict__ b_h) {
    __shared__ float sw[1792];
    __shared__ float sb[64];
    int tid = threadIdx.x;
    for (int i = tid; i < 1792; i += 256) sw[i] = d_wh[4480 + i];
    if (tid < 64) sb[tid] = b_h[tid];
    __syncthreads();

    int pid = blockIdx.x * 256 + tid;
    if (pid >= NTOT) return;
    int b = pid / NPIX, rem = pid % NPIX;
    int f = rem / T_DIM, t = rem % T_DIM;

    const float shift5 = 154.15067982725832f;   // 1000*ln(7/6)
    float src  = (float)f - shift5;
    float lof  = floorf(src);
    float frac = src - lof;
    int   il   = (int)lof;
    const float* hb0 = d_h + ((size_t)(b * 2 + 0) * F_DIM) * T_DIM;
    const float* hb1 = d_h + ((size_t)(b * 2 + 1) * F_DIM) * T_DIM;

    float low[4][7];
    #pragma unroll
    for (int kw = 0; kw < 7; kw++) {
        int tt = t + kw - 3;
        bool tv = (tt >= 0) && (tt < T_DIM);
        float a0 = 0.f, a1 = 0.f, c0 = 0.f, c1 = 0.f, i0 = 0.f, i1 = 0.f;
        if (tv) {
            if (il >= 0 && il < F_DIM)          { a0 = hb0[il * T_DIM + tt];        a1 = hb1[il * T_DIM + tt]; }
            if (il + 1 >= 0 && il + 1 < F_DIM)  { c0 = hb0[(il + 1) * T_DIM + tt];  c1 = hb1[(il + 1) * T_DIM + tt]; }
            i0 = hb0[f * T_DIM + tt]; i1 = hb1[f * T_DIM + tt];
        }
        low[0][kw] = (1.0f - frac) * a0 + frac * c0;
        low[1][kw] = (1.0f - frac) * a1 + frac * c1;
        low[2][kw] = i0;
        low[3][kw] = i1;
    }

    float acc[64];
    #pragma unroll
    for (int o = 0; o < 64; o++) acc[o] = sb[o];
    #pragma unroll
    for (int ci = 0; ci < 4; ci++) {
        #pragma unroll
        for (int kw = 0; kw < 7; kw++) {
            float xv = low[ci][kw];
            const float* wp = &sw[(ci * 7 + kw) * 64];
            #pragma unroll
            for (int o = 0; o < 64; o++) acc[o] += xv * wp[o];
        }
    }

    size_t ridx = (size_t)pid * 64;
    #pragma unroll
    for (int c8 = 0; c8 < 8; c8++) {
        float yv[8], hv[8];
        #pragma unroll
        for (int j = 0; j < 8; j++) {
            float y = acc[c8 * 8 + j];
            y = (y > 0.f) ? y : SLOPE * y;
            yv[j] = y;
            hv[j] = __bfloat162float(__float2bfloat16(y));
        }
        uint4 qh, ql;
        qh.x = pack_bf2(hv[0], hv[1]); qh.y = pack_bf2(hv[2], hv[3]);
        qh.z = pack_bf2(hv[4], hv[5]); qh.w = pack_bf2(hv[6], hv[7]);
        ql.x = pack_bf2(yv[0] - hv[0], yv[1] - hv[1]); ql.y = pack_bf2(yv[2] - hv[2], yv[3] - hv[3]);
        ql.z = pack_bf2(yv[4] - hv[4], yv[5] - hv[5]); ql.w = pack_bf2(yv[6] - hv[6], yv[7] - hv[7]);
        *reinterpret_cast<uint4*>(d_a0h + ridx + c8 * 8) = qh;
        *reinterpret_cast<uint4*>(d_a0l + ridx + c8 * 8) = ql;
    }
}

// ======================= HMMA helper =======================
__device__ __forceinline__ void hmma(float* c, const uint32_t* a, const uint32_t* b) {
    asm volatile(
        "mma.sync.aligned.m16n8k16.row.col.f32.bf16.bf16.f32 "
        "{%0,%1,%2,%3}, {%4,%5,%6,%7}, {%8,%9}, {%0,%1,%2,%3};"
        : "+f"(c[0]), "+f"(c[1]), "+f"(c[2]), "+f"(c[3])
        : "r"(a[0]), "r"(a[1]), "r"(a[2]), "r"(a[3]), "r"(b[0]), "r"(b[1]));
}

// ======================= dilated 3x3 conv, implicit GEMM on mma.sync =======================
// CTA: 128 pixels (4f x 32t) x 64 oc; 8 warps = 4 pixel groups x 2 oc halves.
// Warp tile: 32 pix x 32 oc = 2 m16 x 4 n8 accum frags (32 fp32).
#define AT_STRIDE 144
__global__ __launch_bounds__(256, 2) void conv3_mma(int layer, int D, const float* __restrict__ bs) {
    __shared__ __align__(16) unsigned char smA0[128 * AT_STRIDE];  // hi tile
    __shared__ __align__(16) unsigned char smA1[128 * AT_STRIDE];  // lo tile
    __shared__ float sbias[64];

    int tid = threadIdx.x, wid = tid >> 5, lid = tid & 31;
    int t0 = blockIdx.x * 32, f0 = blockIdx.y * 4, b = blockIdx.z;

    const unsigned short* inH = (layer & 1) ? d_a1h : d_a0h;
    const unsigned short* inL = (layer & 1) ? d_a1l : d_a0l;
    unsigned short* outH = (layer & 1) ? d_a0h : d_a1h;
    unsigned short* outL = (layer & 1) ? d_a0l : d_a1l;

    if (tid < 64) sbias[tid] = bs[layer * 64 + tid];

    int mrow0 = (wid & 3) * 32;       // warp's pixel base within tile
    int ocw   = (wid >> 2) * 32;      // warp's oc base
    int n8b   = (wid >> 2) * 4;       // warp's n8 base

    float acc[2][4][4];
    #pragma unroll
    for (int m = 0; m < 2; m++)
        #pragma unroll
        for (int n = 0; n < 4; n++)
            #pragma unroll
            for (int r = 0; r < 4; r++) acc[m][n][r] = 0.f;

    for (int tap = 0; tap < 9; tap++) {
        int df = (tap / 3 - 1) * D, dt = (tap % 3 - 1) * D;
        __syncthreads();
        // cooperative tile load: 128 rows x 128B (hi & lo), NHWC gmem -> padded smem
        #pragma unroll
        for (int j = 0; j < 4; j++) {
            int v = tid * 4 + j;                  // 0..1023
            int row = v >> 3, cb = (v & 7) * 16;
            int gf = f0 + (row >> 5) + df, gt = t0 + (row & 31) + dt;
            float4 vh = make_float4(0.f, 0.f, 0.f, 0.f), vl = vh;
            if ((unsigned)gf < F_DIM && (unsigned)gt < T_DIM) {
                size_t ridx = (((size_t)b * F_DIM + gf) * T_DIM + gt) * 64;
                vh = *reinterpret_cast<const float4*>((const unsigned char*)inH + ridx * 2 + cb);
                vl = *reinterpret_cast<const float4*>((const unsigned char*)inL + ridx * 2 + cb);
            }
            *reinterpret_cast<float4*>(smA0 + row * AT_STRIDE + cb) = vh;
            *reinterpret_cast<float4*>(smA1 + row * AT_STRIDE + cb) = vl;
        }
        __syncthreads();

        const uint32_t* wbase_h = d_wfh + (((size_t)(layer * 9 + tap) * 4) * 8) * 64;
        const uint32_t* wbase_l = d_wfl + (((size_t)(layer * 9 + tap) * 4) * 8) * 64;

        #pragma unroll
        for (int ks = 0; ks < 4; ks++) {
            // A fragments (hi & lo) via direct lds.b32 (conflict-free: 144B row pad)
            uint32_t ah[2][4], al[2][4];
            #pragma unroll
            for (int m = 0; m < 2; m++) {
                const unsigned char* pH = smA0 + (mrow0 + m * 16 + (lid >> 2)) * AT_STRIDE
                                                + ks * 32 + (lid & 3) * 4;
                const unsigned char* pL = smA1 + (mrow0 + m * 16 + (lid >> 2)) * AT_STRIDE
                                                + ks * 32 + (lid & 3) * 4;
                ah[m][0] = *reinterpret_cast<const uint32_t*>(pH);
                ah[m][1] = *reinterpret_cast<const uint32_t*>(pH + 8 * AT_STRIDE);
                ah[m][2] = *reinterpret_cast<const uint32_t*>(pH + 16);
                ah[m][3] = *reinterpret_cast<const uint32_t*>(pH + 8 * AT_STRIDE + 16);
                al[m][0] = *reinterpret_cast<const uint32_t*>(pL);
                al[m][1] = *reinterpret_cast<const uint32_t*>(pL + 8 * AT_STRIDE);
                al[m][2] = *reinterpret_cast<const uint32_t*>(pL + 16);
                al[m][3] = *reinterpret_cast<const uint32_t*>(pL + 8 * AT_STRIDE + 16);
            }
            // B fragments from gmem (precomputed lane layout, L1/L2 resident)
            uint32_t bh[4][2], bl[4][2];
            #pragma unroll
            for (int n = 0; n < 4; n++) {
                size_t o = ((size_t)ks * 8 + n8b + n) * 64 + lid;
                bh[n][0] = __ldg(wbase_h + o);
                bh[n][1] = __ldg(wbase_h + o + 32);
                bl[n][0] = __ldg(wbase_l + o);
                bl[n][1] = __ldg(wbase_l + o + 32);
            }
            #pragma unroll
            for (int m = 0; m < 2; m++)
                #pragma unroll
                for (int n = 0; n < 4; n++) {
                    hmma(acc[m][n], ah[m], bh[n]);
                    hmma(acc[m][n], ah[m], bl[n]);
                    hmma(acc[m][n], al[m], bh[n]);
                }
        }
    }
    __syncthreads();

    // epilogue: bias + leaky + bf16 hi/lo NHWC store
    #pragma unroll
    for (int m = 0; m < 2; m++) {
        #pragma unroll
        for (int r2 = 0; r2 < 2; r2++) {
            int p = mrow0 + m * 16 + (lid >> 2) + r2 * 8;
            int gf = f0 + (p >> 5), gt = t0 + (p & 31);
            if (gf < F_DIM && gt < T_DIM) {
                size_t ridx = (((size_t)b * F_DIM + gf) * T_DIM + gt) * 64;
                #pragma unroll
                for (int n = 0; n < 4; n++) {
                    int oc = ocw + n * 8 + (lid & 3) * 2;
                    float y0 = acc[m][n][r2 * 2 + 0] + sbias[oc];
                    float y1 = acc[m][n][r2 * 2 + 1] + sbias[oc + 1];
                    y0 = (y0 > 0.f) ? y0 : SLOPE * y0;
                    y1 = (y1 > 0.f) ? y1 : SLOPE * y1;
                    float h0 = __bfloat162float(__float2bfloat16(y0));
                    float h1 = __bfloat162float(__float2bfloat16(y1));
                    *reinterpret_cast<uint32_t*>(outH + ridx + oc) = pack_bf2(h0, h1);
                    *reinterpret_cast<uint32_t*>(outL + ridx + oc) = pack_bf2(y0 - h0, y1 - h1);
                }
            }
        }
    }
}

// ======================= last conv (64 -> 1, 3x3, pad 1) =======================
__global__ __launch_bounds__(256) void last_kernel(float* __restrict__ out) {
    __shared__ float sw[577];
    int tid = threadIdx.x;
    for (int i = tid; i < 577; i += 256) sw[i] = d_wl[i];
    __syncthreads();

    int pid = blockIdx.x * 256 + tid;
    if (pid >= NTOT) return;
    int b = pid / NPIX, rem = pid % NPIX;
    int f = rem / T_DIM, t = rem % T_DIM;

    float acc = sw[576];
    #pragma unroll
    for (int kf = 0; kf < 3; kf++) {
        int fi = f + kf - 1;
        if (fi < 0 || fi >= F_DIM) continue;
        #pragma unroll
        for (int kt = 0; kt < 3; kt++) {
            int ti = t + kt - 1;
            if (ti < 0 || ti >= T_DIM) continue;
            size_t ridx = (((size_t)b * F_DIM + fi) * T_DIM + ti) * 64;
            int wi = kf * 3 + kt;
            #pragma unroll
            for (int c8 = 0; c8 < 8; c8++) {
                uint4 qh = *reinterpret_cast<const uint4*>(d_a0h + ridx + c8 * 8);
                uint4 ql = *reinterpret_cast<const uint4*>(d_a0l + ridx + c8 * 8);
                const uint32_t* ph = &qh.x;
                const uint32_t* pl = &ql.x;
                #pragma unroll
                for (int q = 0; q < 4; q++) {
                    __nv_bfloat162 h2 = *reinterpret_cast<const __nv_bfloat162*>(&ph[q]);
                    __nv_bfloat162 l2 = *reinterpret_cast<const __nv_bfloat162*>(&pl[q]);
                    float2 hf = __bfloat1622float2(h2);
                    float2 lf = __bfloat1622float2(l2);
                    int c = c8 * 8 + q * 2;
                    acc += (hf.x + lf.x) * sw[c * 9 + wi];
                    acc += (hf.y + lf.y) * sw[(c + 1) * 9 + wi];
                }
            }
        }
    }
    out[pid] = acc;
}

// ======================= launch =======================
extern "C" void kernel_launch(void* const* d_in, const int* in_sizes, int n_in,
                              void* d_out, int out_size) {
    const float* x      = (const float*)d_in[0];
    const float* v_h    = (const float*)d_in[1];
    const float* g_h    = (const float*)d_in[2];
    const float* b_h    = (const float*)d_in[3];
    const float* vs     = (const float*)d_in[4];
    const float* gs     = (const float*)d_in[5];
    const float* bs     = (const float*)d_in[6];
    const float* v_last = (const float*)d_in[7];
    const float* g_last = (const float*)d_in[8];
    const float* b_last = (const float*)d_in[9];
    float* out = (float*)d_out;

    prep_kernel<<<577, 128>>>(v_h, g_h, vs, gs, v_last, g_last, b_last);
    wfrag_kernel<<<dim3(8, 9), 256>>>();
    stft_kernel<<<dim3(257, NB), 256>>>(x);
    conv1_kernel<<<(NTOT + 255) / 256, 256>>>(b_h);

    dim3 cg(9, 65, NB);
    for (int L = 0; L < 8; L++)
        conv3_mma<<<cg, 256>>>(L, L + 1, bs);

    last_kernel<<<(NTOT + 255) / 256, 256>>>(out);
}

// round 4
// speedup vs baseline: 3.9166x; 1.2471x over previous
#include <cuda_runtime.h>
#include <cuda_bf16.h>
#include <stdint.h>
#include <math.h>

#define F_DIM 257
#define T_DIM 257
#define NB 4
#define NPIX (F_DIM * T_DIM)        // 66049
#define NTOT (NB * NPIX)            // 264196
#define SLOPE 0.2f

// ======================= scratch =======================
__device__ float d_h[NB * 2 * NPIX];                                // STFT (B,2,F,T)
__device__ __align__(16) unsigned short d_a0h[(size_t)NTOT * 64];   // NHWC bf16 hi
__device__ __align__(16) unsigned short d_a0l[(size_t)NTOT * 64];   // NHWC bf16 lo
__device__ __align__(16) unsigned short d_a1h[(size_t)NTOT * 64];
__device__ __align__(16) unsigned short d_a1l[(size_t)NTOT * 64];
__device__ float d_wh[14 * 7 * 64];                                 // conv1 fp32 [ci][kw][o]
__device__ float d_wm[8 * 64 * 9 * 64];                             // mid fp32 [L][(c*9+tap)*64+o]
__device__ uint32_t d_wfh[8 * 9 * 4 * 8 * 2 * 32];                  // B frags hi [L][tap][ks][n8][reg][lane]
__device__ uint32_t d_wfl[8 * 9 * 4 * 8 * 2 * 32];                  // B frags lo
__device__ float d_wl[578];                                         // last conv fp32

// ======================= small PTX helpers =======================
__device__ __forceinline__ uint32_t smem_u32(const void* p) {
    uint32_t a;
    asm("{ .reg .u64 t; cvta.to.shared.u64 t, %1; cvt.u32.u64 %0, t; }" : "=r"(a) : "l"(p));
    return a;
}
__device__ __forceinline__ void cp16(uint32_t dst, const void* src, int src_bytes) {
    asm volatile("cp.async.cg.shared.global [%0], [%1], 16, %2;"
                 :: "r"(dst), "l"(src), "r"(src_bytes) : "memory");
}
#define CP_COMMIT() asm volatile("cp.async.commit_group;" ::: "memory")
#define CP_WAIT(n)  asm volatile("cp.async.wait_group %0;" :: "n"(n) : "memory")

__device__ __forceinline__ void hmma(float* c, const uint32_t* a, const uint32_t* b) {
    asm volatile(
        "mma.sync.aligned.m16n8k16.row.col.f32.bf16.bf16.f32 "
        "{%0,%1,%2,%3}, {%4,%5,%6,%7}, {%8,%9}, {%0,%1,%2,%3};"
        : "+f"(c[0]), "+f"(c[1]), "+f"(c[2]), "+f"(c[3])
        : "r"(a[0]), "r"(a[1]), "r"(a[2]), "r"(a[3]), "r"(b[0]), "r"(b[1]));
}

__device__ __forceinline__ uint32_t pack_bf2(float a, float b) {
    __nv_bfloat162 h = __floats2bfloat162_rn(a, b);
    return *reinterpret_cast<uint32_t*>(&h);
}

// ======================= weight-norm prep =======================
__global__ void prep_kernel(const float* __restrict__ v_h, const float* __restrict__ g_h,
                            const float* __restrict__ vs,  const float* __restrict__ gs,
                            const float* __restrict__ v_last, const float* __restrict__ g_last,
                            const float* __restrict__ b_last) {
    __shared__ float red[128];
    int bid = blockIdx.x, tid = threadIdx.x;
    const float* base; int n; float g; int o = 0;
    if (bid < 64)        { o = bid; base = v_h + o * 98; n = 98; g = g_h[o]; }
    else if (bid < 576)  { int L = (bid - 64) >> 6; o = (bid - 64) & 63;
                           base = vs + (size_t)(L * 64 + o) * 576; n = 576; g = gs[L * 64 + o]; }
    else                 { base = v_last; n = 576; g = g_last[0]; }

    float s = 0.f;
    for (int i = tid; i < n; i += 128) { float v = base[i]; s += v * v; }
    red[tid] = s; __syncthreads();
    for (int k = 64; k > 0; k >>= 1) { if (tid < k) red[tid] += red[tid + k]; __syncthreads(); }
    float scale = g * rsqrtf(red[0]);

    if (bid < 64) {
        for (int i = tid; i < n; i += 128) d_wh[i * 64 + o] = base[i] * scale;
    } else if (bid < 576) {
        int L = (bid - 64) >> 6;
        for (int i = tid; i < n; i += 128) d_wm[(size_t)L * 36864 + i * 64 + o] = base[i] * scale;
    } else {
        for (int i = tid; i < n; i += 128) d_wl[i] = base[i] * scale;
        if (tid == 0) d_wl[576] = b_last[0];
    }
}

// ======================= build B fragments in mma lane layout =======================
__global__ void wfrag_kernel() {
    int L = blockIdx.x, tap = blockIdx.y;
    const float* wm = d_wm + (size_t)L * 36864;
    for (int e = threadIdx.x; e < 2048; e += 256) {
        int lane = e & 31, reg = (e >> 5) & 1, n8 = (e >> 6) & 7, ks = (e >> 9) & 3;
        int k0 = ks * 16 + reg * 8 + (lane & 3) * 2;
        int nn = n8 * 8 + (lane >> 2);
        float w0 = wm[(k0 * 9 + tap) * 64 + nn];
        float w1 = wm[((k0 + 1) * 9 + tap) * 64 + nn];
        __nv_bfloat16 h0 = __float2bfloat16(w0), h1 = __float2bfloat16(w1);
        __nv_bfloat16 l0 = __float2bfloat16(w0 - __bfloat162float(h0));
        __nv_bfloat16 l1 = __float2bfloat16(w1 - __bfloat162float(h1));
        size_t idx = ((((size_t)(L * 9 + tap) * 4 + ks) * 8 + n8) * 2 + reg) * 32 + lane;
        d_wfh[idx] = ((uint32_t)__bfloat16_as_ushort(h1) << 16) | __bfloat16_as_ushort(h0);
        d_wfl[idx] = ((uint32_t)__bfloat16_as_ushort(l1) << 16) | __bfloat16_as_ushort(l0);
    }
}

// ======================= STFT =======================
__global__ void stft_kernel(const float* __restrict__ x) {
    __shared__ float s[512], ct[512], st[512];
    int t = blockIdx.x, b = blockIdx.y, tid = threadIdx.x;
    const float* xb = x + (size_t)b * 65536;
    for (int n = tid; n < 512; n += 256) {
        int idx = t * 256 + n - 256;
        if (idx < 0) idx = -idx;
        if (idx >= 65536) idx = 131070 - idx;
        float w = 0.5f - 0.5f * cospif(n * (1.0f / 256.0f));
        s[n] = xb[idx] * w;
        float ss, cc;
        sincospif(n * (1.0f / 256.0f), &ss, &cc);
        ct[n] = cc; st[n] = ss;
    }
    __syncthreads();
    for (int f = tid; f < 257; f += 256) {
        float re = 0.f, im = 0.f;
        int m = 0;
        #pragma unroll 8
        for (int n = 0; n < 512; n++) {
            float v = s[n];
            re += v * ct[m];
            im -= v * st[m];
            m = (m + f) & 511;
        }
        d_h[((size_t)(b * 2 + 0) * F_DIM + f) * T_DIM + t] = re;
        d_h[((size_t)(b * 2 + 1) * F_DIM + f) * T_DIM + t] = im;
    }
}

// ======================= fused lower + conv1 + leaky -> NHWC bf16 hi/lo =======================
__global__ __launch_bounds__(256) void conv1_kernel(const float* __restrict__ b_h) {
    __shared__ float sw[1792];
    __shared__ float sb[64];
    int tid = threadIdx.x;
    for (int i = tid; i < 1792; i += 256) sw[i] = d_wh[4480 + i];
    if (tid < 64) sb[tid] = b_h[tid];
    __syncthreads();

    int pid = blockIdx.x * 256 + tid;
    if (pid >= NTOT) return;
    int b = pid / NPIX, rem = pid % NPIX;
    int f = rem / T_DIM, t = rem % T_DIM;

    const float shift5 = 154.15067982725832f;   // 1000*ln(7/6)
    float src  = (float)f - shift5;
    float lof  = floorf(src);
    float frac = src - lof;
    int   il   = (int)lof;
    const float* hb0 = d_h + ((size_t)(b * 2 + 0) * F_DIM) * T_DIM;
    const float* hb1 = d_h + ((size_t)(b * 2 + 1) * F_DIM) * T_DIM;

    float low[4][7];
    #pragma unroll
    for (int kw = 0; kw < 7; kw++) {
        int tt = t + kw - 3;
        bool tv = (tt >= 0) && (tt < T_DIM);
        float a0 = 0.f, a1 = 0.f, c0 = 0.f, c1 = 0.f, i0 = 0.f, i1 = 0.f;
        if (tv) {
            if (il >= 0 && il < F_DIM)          { a0 = hb0[il * T_DIM + tt];        a1 = hb1[il * T_DIM + tt]; }
            if (il + 1 >= 0 && il + 1 < F_DIM)  { c0 = hb0[(il + 1) * T_DIM + tt];  c1 = hb1[(il + 1) * T_DIM + tt]; }
            i0 = hb0[f * T_DIM + tt]; i1 = hb1[f * T_DIM + tt];
        }
        low[0][kw] = (1.0f - frac) * a0 + frac * c0;
        low[1][kw] = (1.0f - frac) * a1 + frac * c1;
        low[2][kw] = i0;
        low[3][kw] = i1;
    }

    float acc[64];
    #pragma unroll
    for (int o = 0; o < 64; o++) acc[o] = sb[o];
    #pragma unroll
    for (int ci = 0; ci < 4; ci++) {
        #pragma unroll
        for (int kw = 0; kw < 7; kw++) {
            float xv = low[ci][kw];
            const float* wp = &sw[(ci * 7 + kw) * 64];
            #pragma unroll
            for (int o = 0; o < 64; o++) acc[o] += xv * wp[o];
        }
    }

    size_t ridx = (size_t)pid * 64;
    #pragma unroll
    for (int c8 = 0; c8 < 8; c8++) {
        float yv[8], hv[8];
        #pragma unroll
        for (int j = 0; j < 8; j++) {
            float y = acc[c8 * 8 + j];
            y = (y > 0.f) ? y : SLOPE * y;
            yv[j] = y;
            hv[j] = __bfloat162float(__float2bfloat16(y));
        }
        uint4 qh, ql;
        qh.x = pack_bf2(hv[0], hv[1]); qh.y = pack_bf2(hv[2], hv[3]);
        qh.z = pack_bf2(hv[4], hv[5]); qh.w = pack_bf2(hv[6], hv[7]);
        ql.x = pack_bf2(yv[0] - hv[0], yv[1] - hv[1]); ql.y = pack_bf2(yv[2] - hv[2], yv[3] - hv[3]);
        ql.z = pack_bf2(yv[4] - hv[4], yv[5] - hv[5]); ql.w = pack_bf2(yv[6] - hv[6], yv[7] - hv[7]);
        *reinterpret_cast<uint4*>(d_a0h + ridx + c8 * 8) = qh;
        *reinterpret_cast<uint4*>(d_a0l + ridx + c8 * 8) = ql;
    }
}

// ======================= dilated 3x3 conv: pipelined halo implicit GEMM =======================
// CTA: 128 pixels (4f x 32t) x 64 oc; 8 warps = 4 pixel groups x 2 oc halves.
// Per kf row-group: halo tile 4f x (32+2D)t loaded ONCE (cp.async double buffer);
// the 3 kt taps read it at column offset kt*D. A rows stored at stride 144B (conflict-free).
#define AT_STRIDE 144
#define STAGE_BYTES (192 * AT_STRIDE)          // 4 pf rows x 48 t-slots
#define SM_BIAS_OFF (4 * STAGE_BYTES)          // 110592
#define CONV3_SMEM (SM_BIAS_OFF + 256)

__global__ __launch_bounds__(256, 2) void conv3_mma(int layer, int D, const float* __restrict__ bs) {
    extern __shared__ __align__(16) unsigned char smem[];
    uint32_t sb = smem_u32(smem);
    int tid = threadIdx.x, wid = tid >> 5, lid = tid & 31;
    int t0 = blockIdx.x * 32, f0 = blockIdx.y * 4, b = blockIdx.z;
    const int HW = 32 + 2 * D;

    const unsigned short* inH = (layer & 1) ? d_a1h : d_a0h;
    const unsigned short* inL = (layer & 1) ? d_a1l : d_a0l;
    unsigned short* outH = (layer & 1) ? d_a0h : d_a1h;
    unsigned short* outL = (layer & 1) ? d_a0l : d_a1l;

    if (tid < 64) *reinterpret_cast<float*>(smem + SM_BIAS_OFF + tid * 4) = bs[layer * 64 + tid];

    int mrow0 = (wid & 3) * 32;
    int ocw   = (wid >> 2) * 32;
    int n8b   = (wid >> 2) * 4;

    float acc[2][4][4];
    #pragma unroll
    for (int m = 0; m < 2; m++)
        #pragma unroll
        for (int n = 0; n < 4; n++)
            #pragma unroll
            for (int r = 0; r < 4; r++) acc[m][n][r] = 0.f;

    // ---- halo group loader (cp.async) ----
    auto issue_group = [&](int kf, int stage) {
        int df = (kf - 1) * D;
        uint32_t baseH = sb + (uint32_t)stage * 2u * STAGE_BYTES;
        uint32_t baseL = baseH + STAGE_BYTES;
        #pragma unroll
        for (int pf = 0; pf < 4; pf++) {
            int gf = f0 + pf + df;
            bool fok = (unsigned)gf < F_DIM;
            for (int idx = tid; idx < HW * 8; idx += 256) {
                int tl = idx >> 3, cb = (idx & 7) * 16;
                int gt = t0 - D + tl;
                bool ok = fok && ((unsigned)gt < T_DIM);
                size_t ridx = ok ? ((((size_t)b * F_DIM + gf) * T_DIM + gt) * 64) : 0;
                uint32_t off = (uint32_t)(pf * 48 + tl) * AT_STRIDE + cb;
                cp16(baseH + off, (const unsigned char*)inH + ridx * 2 + cb, ok ? 16 : 0);
                cp16(baseL + off, (const unsigned char*)inL + ridx * 2 + cb, ok ? 16 : 0);
            }
        }
        CP_COMMIT();
    };

    issue_group(0, 0);
    for (int g = 0; g < 3; g++) {
        if (g < 2) { issue_group(g + 1, (g + 1) & 1); CP_WAIT(1); }
        else       { CP_WAIT(0); }
        __syncthreads();

        uint32_t aH = sb + (uint32_t)(g & 1) * 2u * STAGE_BYTES;
        uint32_t aL = aH + STAGE_BYTES;

        for (int kt = 0; kt < 3; kt++) {
            int tap = g * 3 + kt;
            const uint32_t* wbh = d_wfh + (size_t)(layer * 9 + tap) * 2048;
            const uint32_t* wbl = d_wfl + (size_t)(layer * 9 + tap) * 2048;
            int coff = kt * D;

            #pragma unroll
            for (int ks = 0; ks < 4; ks++) {
                uint32_t ah[2][4], al[2][4];
                #pragma unroll
                for (int m = 0; m < 2; m++) {
                    int p = mrow0 + m * 16 + (lid >> 2);
                    uint32_t hrow = (uint32_t)((p >> 5) * 48 + (p & 31) + coff);
                    uint32_t ba = hrow * AT_STRIDE + ks * 32 + (lid & 3) * 4;
                    ah[m][0] = *reinterpret_cast<const uint32_t*>(smem + (aH - sb) + ba);
                    ah[m][1] = *reinterpret_cast<const uint32_t*>(smem + (aH - sb) + ba + 8 * AT_STRIDE);
                    ah[m][2] = *reinterpret_cast<const uint32_t*>(smem + (aH - sb) + ba + 16);
                    ah[m][3] = *reinterpret_cast<const uint32_t*>(smem + (aH - sb) + ba + 8 * AT_STRIDE + 16);
                    al[m][0] = *reinterpret_cast<const uint32_t*>(smem + (aL - sb) + ba);
                    al[m][1] = *reinterpret_cast<const uint32_t*>(smem + (aL - sb) + ba + 8 * AT_STRIDE);
                    al[m][2] = *reinterpret_cast<const uint32_t*>(smem + (aL - sb) + ba + 16);
                    al[m][3] = *reinterpret_cast<const uint32_t*>(smem + (aL - sb) + ba + 8 * AT_STRIDE + 16);
                }
                uint32_t bh[4][2], bl[4][2];
                #pragma unroll
                for (int n = 0; n < 4; n++) {
                    size_t o = ((size_t)ks * 8 + n8b + n) * 64 + lid;
                    bh[n][0] = __ldg(wbh + o);
                    bh[n][1] = __ldg(wbh + o + 32);
                    bl[n][0] = __ldg(wbl + o);
                    bl[n][1] = __ldg(wbl + o + 32);
                }
                #pragma unroll
                for (int m = 0; m < 2; m++)
                    #pragma unroll
                    for (int n = 0; n < 4; n++) {
                        hmma(acc[m][n], ah[m], bh[n]);
                        hmma(acc[m][n], ah[m], bl[n]);
                        hmma(acc[m][n], al[m], bh[n]);
                    }
            }
        }
        __syncthreads();
    }

    // ---- epilogue: bias + leaky + bf16 hi/lo NHWC store ----
    const float* bias = reinterpret_cast<const float*>(smem + SM_BIAS_OFF);
    #pragma unroll
    for (int m = 0; m < 2; m++) {
        #pragma unroll
        for (int r2 = 0; r2 < 2; r2++) {
            int p = mrow0 + m * 16 + (lid >> 2) + r2 * 8;
            int gf = f0 + (p >> 5), gt = t0 + (p & 31);
            if (gf < F_DIM && gt < T_DIM) {
                size_t ridx = (((size_t)b * F_DIM + gf) * T_DIM + gt) * 64;
                #pragma unroll
                for (int n = 0; n < 4; n++) {
                    int oc = ocw + n * 8 + (lid & 3) * 2;
                    float y0 = acc[m][n][r2 * 2 + 0] + bias[oc];
                    float y1 = acc[m][n][r2 * 2 + 1] + bias[oc + 1];
                    y0 = (y0 > 0.f) ? y0 : SLOPE * y0;
                    y1 = (y1 > 0.f) ? y1 : SLOPE * y1;
                    float h0 = __bfloat162float(__float2bfloat16(y0));
                    float h1 = __bfloat162float(__float2bfloat16(y1));
                    *reinterpret_cast<uint32_t*>(outH + ridx + oc) = pack_bf2(h0, h1);
                    *reinterpret_cast<uint32_t*>(outL + ridx + oc) = pack_bf2(y0 - h0, y1 - h1);
                }
            }
        }
    }
}

// ======================= last conv (64 -> 1, 3x3, pad 1) =======================
__global__ __launch_bounds__(256) void last_kernel(float* __restrict__ out) {
    __shared__ float sw[577];
    int tid = threadIdx.x;
    for (int i = tid; i < 577; i += 256) sw[i] = d_wl[i];
    __syncthreads();

    int pid = blockIdx.x * 256 + tid;
    if (pid >= NTOT) return;
    int b = pid / NPIX, rem = pid % NPIX;
    int f = rem / T_DIM, t = rem % T_DIM;

    float acc = sw[576];
    #pragma unroll
    for (int kf = 0; kf < 3; kf++) {
        int fi = f + kf - 1;
        if (fi < 0 || fi >= F_DIM) continue;
        #pragma unroll
        for (int kt = 0; kt < 3; kt++) {
            int ti = t + kt - 1;
            if (ti < 0 || ti >= T_DIM) continue;
            size_t ridx = (((size_t)b * F_DIM + fi) * T_DIM + ti) * 64;
            int wi = kf * 3 + kt;
            #pragma unroll
            for (int c8 = 0; c8 < 8; c8++) {
                uint4 qh = *reinterpret_cast<const uint4*>(d_a0h + ridx + c8 * 8);
                uint4 ql = *reinterpret_cast<const uint4*>(d_a0l + ridx + c8 * 8);
                const uint32_t* ph = &qh.x;
                const uint32_t* pl = &ql.x;
                #pragma unroll
                for (int q = 0; q < 4; q++) {
                    __nv_bfloat162 h2 = *reinterpret_cast<const __nv_bfloat162*>(&ph[q]);
                    __nv_bfloat162 l2 = *reinterpret_cast<const __nv_bfloat162*>(&pl[q]);
                    float2 hf = __bfloat1622float2(h2);
                    float2 lf = __bfloat1622float2(l2);
                    int c = c8 * 8 + q * 2;
                    acc += (hf.x + lf.x) * sw[c * 9 + wi];
                    acc += (hf.y + lf.y) * sw[(c + 1) * 9 + wi];
                }
            }
        }
    }
    out[pid] = acc;
}

// ======================= launch =======================
extern "C" void kernel_launch(void* const* d_in, const int* in_sizes, int n_in,
                              void* d_out, int out_size) {
    const float* x      = (const float*)d_in[0];
    const float* v_h    = (const float*)d_in[1];
    const float* g_h    = (const float*)d_in[2];
    const float* b_h    = (const float*)d_in[3];
    const float* vs     = (const float*)d_in[4];
    const float* gs     = (const float*)d_in[5];
    const float* bs     = (const float*)d_in[6];
    const float* v_last = (const float*)d_in[7];
    const float* g_last = (const float*)d_in[8];
    const float* b_last = (const float*)d_in[9];
    float* out = (float*)d_out;

    cudaFuncSetAttribute(conv3_mma, cudaFuncAttributeMaxDynamicSharedMemorySize, CONV3_SMEM);

    prep_kernel<<<577, 128>>>(v_h, g_h, vs, gs, v_last, g_last, b_last);
    wfrag_kernel<<<dim3(8, 9), 256>>>();
    stft_kernel<<<dim3(257, NB), 256>>>(x);
    conv1_kernel<<<(NTOT + 255) / 256, 256>>>(b_h);

    dim3 cg(9, 65, NB);
    for (int L = 0; L < 8; L++)
        conv3_mma<<<cg, 256, CONV3_SMEM>>>(L, L + 1, bs);

    last_kernel<<<(NTOT + 255) / 256, 256>>>(out);
}

// round 5
// speedup vs baseline: 4.4201x; 1.1286x over previous
#include <cuda_runtime.h>
#include <cuda_bf16.h>
#include <stdint.h>
#include <math.h>

#define F_DIM 257
#define T_DIM 257
#define NB 4
#define NPIX (F_DIM * T_DIM)        // 66049
#define NTOT (NB * NPIX)            // 264196
#define SLOPE 0.2f

// ======================= scratch =======================
__device__ float d_h[NB * 2 * NPIX];                                // STFT (B,2,F,T)
__device__ __align__(16) unsigned short d_a0h[(size_t)NTOT * 64];   // NHWC bf16 hi
__device__ __align__(16) unsigned short d_a0l[(size_t)NTOT * 64];   // NHWC bf16 lo
__device__ __align__(16) unsigned short d_a1h[(size_t)NTOT * 64];
__device__ __align__(16) unsigned short d_a1l[(size_t)NTOT * 64];
__device__ float d_wh[14 * 7 * 64];                                 // conv1 fp32 [ci][kw][o]
__device__ float d_wm[8 * 64 * 9 * 64];                             // mid fp32 [L][(c*9+tap)*64+o]
__device__ __align__(16) uint32_t d_wf[8 * 9 * 4 * 8 * 128];        // B frags [L*9+tap][ks][n8][lane][4]
__device__ float d_wl[578];                                         // last conv fp32

// ======================= small PTX helpers =======================
__device__ __forceinline__ uint32_t smem_u32(const void* p) {
    uint32_t a;
    asm("{ .reg .u64 t; cvta.to.shared.u64 t, %1; cvt.u32.u64 %0, t; }" : "=r"(a) : "l"(p));
    return a;
}
__device__ __forceinline__ void cp16(uint32_t dst, const void* src, int src_bytes) {
    asm volatile("cp.async.cg.shared.global [%0], [%1], 16, %2;"
                 :: "r"(dst), "l"(src), "r"(src_bytes) : "memory");
}
#define CP_COMMIT() asm volatile("cp.async.commit_group;" ::: "memory")
#define CP_WAIT(n)  asm volatile("cp.async.wait_group %0;" :: "n"(n) : "memory")

__device__ __forceinline__ void hmma(float* c, const uint32_t* a, const uint32_t* b) {
    asm volatile(
        "mma.sync.aligned.m16n8k16.row.col.f32.bf16.bf16.f32 "
        "{%0,%1,%2,%3}, {%4,%5,%6,%7}, {%8,%9}, {%0,%1,%2,%3};"
        : "+f"(c[0]), "+f"(c[1]), "+f"(c[2]), "+f"(c[3])
        : "r"(a[0]), "r"(a[1]), "r"(a[2]), "r"(a[3]), "r"(b[0]), "r"(b[1]));
}
__device__ __forceinline__ void ldmx4(uint32_t* r, uint32_t addr) {
    asm volatile("ldmatrix.sync.aligned.m8n8.x4.shared.b16 {%0,%1,%2,%3}, [%4];"
        : "=r"(r[0]), "=r"(r[1]), "=r"(r[2]), "=r"(r[3]) : "r"(addr));
}
__device__ __forceinline__ uint32_t pack_bf2(float a, float b) {
    __nv_bfloat162 h = __floats2bfloat162_rn(a, b);
    return *reinterpret_cast<uint32_t*>(&h);
}

// ======================= weight-norm prep =======================
__global__ void prep_kernel(const float* __restrict__ v_h, const float* __restrict__ g_h,
                            const float* __restrict__ vs,  const float* __restrict__ gs,
                            const float* __restrict__ v_last, const float* __restrict__ g_last,
                            const float* __restrict__ b_last) {
    __shared__ float red[128];
    int bid = blockIdx.x, tid = threadIdx.x;
    const float* base; int n; float g; int o = 0;
    if (bid < 64)        { o = bid; base = v_h + o * 98; n = 98; g = g_h[o]; }
    else if (bid < 576)  { int L = (bid - 64) >> 6; o = (bid - 64) & 63;
                           base = vs + (size_t)(L * 64 + o) * 576; n = 576; g = gs[L * 64 + o]; }
    else                 { base = v_last; n = 576; g = g_last[0]; }

    float s = 0.f;
    for (int i = tid; i < n; i += 128) { float v = base[i]; s += v * v; }
    red[tid] = s; __syncthreads();
    for (int k = 64; k > 0; k >>= 1) { if (tid < k) red[tid] += red[tid + k]; __syncthreads(); }
    float scale = g * rsqrtf(red[0]);

    if (bid < 64) {
        for (int i = tid; i < n; i += 128) d_wh[i * 64 + o] = base[i] * scale;
    } else if (bid < 576) {
        int L = (bid - 64) >> 6;
        for (int i = tid; i < n; i += 128) d_wm[(size_t)L * 36864 + i * 64 + o] = base[i] * scale;
    } else {
        for (int i = tid; i < n; i += 128) d_wl[i] = base[i] * scale;
        if (tid == 0) d_wl[576] = b_last[0];
    }
}

// ======================= build B fragments: one uint4 per lane =======================
// lane holds {hi_reg0, hi_reg1, lo_reg0, lo_reg1} for n = n8*8 + lane/4, k pairs at
// ks*16 + reg*8 + (lane%4)*2.
__global__ void wfrag_kernel() {
    int L = blockIdx.x, tap = blockIdx.y;
    const float* wm = d_wm + (size_t)L * 36864;
    for (int e = threadIdx.x; e < 1024; e += 256) {
        int lane = e & 31, n8 = (e >> 5) & 7, ks = e >> 8;
        int nn = n8 * 8 + (lane >> 2);
        uint32_t w[4];
        #pragma unroll
        for (int r = 0; r < 2; r++) {
            int k0 = ks * 16 + r * 8 + (lane & 3) * 2;
            float w0 = wm[(k0 * 9 + tap) * 64 + nn];
            float w1 = wm[((k0 + 1) * 9 + tap) * 64 + nn];
            __nv_bfloat16 h0 = __float2bfloat16(w0), h1 = __float2bfloat16(w1);
            __nv_bfloat16 l0 = __float2bfloat16(w0 - __bfloat162float(h0));
            __nv_bfloat16 l1 = __float2bfloat16(w1 - __bfloat162float(h1));
            w[r]     = ((uint32_t)__bfloat16_as_ushort(h1) << 16) | __bfloat16_as_ushort(h0);
            w[2 + r] = ((uint32_t)__bfloat16_as_ushort(l1) << 16) | __bfloat16_as_ushort(l0);
        }
        size_t idx = (((size_t)(L * 9 + tap) * 4 + ks) * 8 + n8) * 128 + lane * 4;
        *reinterpret_cast<uint4*>(d_wf + idx) = make_uint4(w[0], w[1], w[2], w[3]);
    }
}

// ======================= STFT =======================
__global__ void stft_kernel(const float* __restrict__ x) {
    __shared__ float s[512], ct[512], st[512];
    int t = blockIdx.x, b = blockIdx.y, tid = threadIdx.x;
    const float* xb = x + (size_t)b * 65536;
    for (int n = tid; n < 512; n += 256) {
        int idx = t * 256 + n - 256;
        if (idx < 0) idx = -idx;
        if (idx >= 65536) idx = 131070 - idx;
        float w = 0.5f - 0.5f * cospif(n * (1.0f / 256.0f));
        s[n] = xb[idx] * w;
        float ss, cc;
        sincospif(n * (1.0f / 256.0f), &ss, &cc);
        ct[n] = cc; st[n] = ss;
    }
    __syncthreads();
    for (int f = tid; f < 257; f += 256) {
        float re = 0.f, im = 0.f;
        int m = 0;
        #pragma unroll 8
        for (int n = 0; n < 512; n++) {
            float v = s[n];
            re += v * ct[m];
            im -= v * st[m];
            m = (m + f) & 511;
        }
        d_h[((size_t)(b * 2 + 0) * F_DIM + f) * T_DIM + t] = re;
        d_h[((size_t)(b * 2 + 1) * F_DIM + f) * T_DIM + t] = im;
    }
}

// ======================= fused lower + conv1 + leaky -> NHWC bf16 hi/lo =======================
__global__ __launch_bounds__(256) void conv1_kernel(const float* __restrict__ b_h) {
    __shared__ float sw[1792];
    __shared__ float sb[64];
    int tid = threadIdx.x;
    for (int i = tid; i < 1792; i += 256) sw[i] = d_wh[4480 + i];
    if (tid < 64) sb[tid] = b_h[tid];
    __syncthreads();

    int pid = blockIdx.x * 256 + tid;
    if (pid >= NTOT) return;
    int b = pid / NPIX, rem = pid % NPIX;
    int f = rem / T_DIM, t = rem % T_DIM;

    const float shift5 = 154.15067982725832f;   // 1000*ln(7/6)
    float src  = (float)f - shift5;
    float lof  = floorf(src);
    float frac = src - lof;
    int   il   = (int)lof;
    const float* hb0 = d_h + ((size_t)(b * 2 + 0) * F_DIM) * T_DIM;
    const float* hb1 = d_h + ((size_t)(b * 2 + 1) * F_DIM) * T_DIM;

    float low[4][7];
    #pragma unroll
    for (int kw = 0; kw < 7; kw++) {
        int tt = t + kw - 3;
        bool tv = (tt >= 0) && (tt < T_DIM);
        float a0 = 0.f, a1 = 0.f, c0 = 0.f, c1 = 0.f, i0 = 0.f, i1 = 0.f;
        if (tv) {
            if (il >= 0 && il < F_DIM)          { a0 = hb0[il * T_DIM + tt];        a1 = hb1[il * T_DIM + tt]; }
            if (il + 1 >= 0 && il + 1 < F_DIM)  { c0 = hb0[(il + 1) * T_DIM + tt];  c1 = hb1[(il + 1) * T_DIM + tt]; }
            i0 = hb0[f * T_DIM + tt]; i1 = hb1[f * T_DIM + tt];
        }
        low[0][kw] = (1.0f - frac) * a0 + frac * c0;
        low[1][kw] = (1.0f - frac) * a1 + frac * c1;
        low[2][kw] = i0;
        low[3][kw] = i1;
    }

    float acc[64];
    #pragma unroll
    for (int o = 0; o < 64; o++) acc[o] = sb[o];
    #pragma unroll
    for (int ci = 0; ci < 4; ci++) {
        #pragma unroll
        for (int kw = 0; kw < 7; kw++) {
            float xv = low[ci][kw];
            const float* wp = &sw[(ci * 7 + kw) * 64];
            #pragma unroll
            for (int o = 0; o < 64; o++) acc[o] += xv * wp[o];
        }
    }

    size_t ridx = (size_t)pid * 64;
    #pragma unroll
    for (int c8 = 0; c8 < 8; c8++) {
        float yv[8], hv[8];
        #pragma unroll
        for (int j = 0; j < 8; j++) {
            float y = acc[c8 * 8 + j];
            y = (y > 0.f) ? y : SLOPE * y;
            yv[j] = y;
            hv[j] = __bfloat162float(__float2bfloat16(y));
        }
        uint4 qh, ql;
        qh.x = pack_bf2(hv[0], hv[1]); qh.y = pack_bf2(hv[2], hv[3]);
        qh.z = pack_bf2(hv[4], hv[5]); qh.w = pack_bf2(hv[6], hv[7]);
        ql.x = pack_bf2(yv[0] - hv[0], yv[1] - hv[1]); ql.y = pack_bf2(yv[2] - hv[2], yv[3] - hv[3]);
        ql.z = pack_bf2(yv[4] - hv[4], yv[5] - hv[5]); ql.w = pack_bf2(yv[6] - hv[6], yv[7] - hv[7]);
        *reinterpret_cast<uint4*>(d_a0h + ridx + c8 * 8) = qh;
        *reinterpret_cast<uint4*>(d_a0l + ridx + c8 * 8) = ql;
    }
}

// ======================= dilated 3x3 conv: pipelined halo implicit GEMM =======================
// CTA: 128 pixels (4f x 32t) x 64 oc; 8 warps = 4 pixel groups x 2 oc halves.
// Per kf row-group: halo tile 4f x (32+2D)t loaded ONCE (cp.async double buffer);
// 3 kt taps read at column offset kt*D. A frags via ldmatrix.x4, B frags via LDG.128.
#define AT_STRIDE 144
#define STAGE_BYTES (192 * AT_STRIDE)          // 4 pf rows x 48 t-slots
#define SM_BIAS_OFF (4 * STAGE_BYTES)          // 110592
#define CONV3_SMEM (SM_BIAS_OFF + 256)

__global__ __launch_bounds__(256, 2) void conv3_mma(int layer, int D, const float* __restrict__ bs) {
    extern __shared__ __align__(16) unsigned char smem[];
    uint32_t sb = smem_u32(smem);
    int tid = threadIdx.x, wid = tid >> 5, lid = tid & 31;
    int t0 = blockIdx.x * 32, f0 = blockIdx.y * 4, b = blockIdx.z;
    const int HW = 32 + 2 * D;

    const unsigned short* inH = (layer & 1) ? d_a1h : d_a0h;
    const unsigned short* inL = (layer & 1) ? d_a1l : d_a0l;
    unsigned short* outH = (layer & 1) ? d_a0h : d_a1h;
    unsigned short* outL = (layer & 1) ? d_a0l : d_a1l;

    if (tid < 64) *reinterpret_cast<float*>(smem + SM_BIAS_OFF + tid * 4) = bs[layer * 64 + tid];

    int mrow0 = (wid & 3) * 32;
    int ocw   = (wid >> 2) * 32;
    int n8b   = (wid >> 2) * 4;

    // ldmatrix per-lane address component (matrix i: lanes 8i..8i+7 give row addrs)
    int mat = lid >> 3, rowin = lid & 7;
    uint32_t laneoff = (uint32_t)(((mat & 1) * 8 + rowin) * AT_STRIDE + (mat >> 1) * 16);
    uint32_t pfoff   = (uint32_t)((mrow0 >> 5) * 48 * AT_STRIDE);

    float acc[2][4][4];
    #pragma unroll
    for (int m = 0; m < 2; m++)
        #pragma unroll
        for (int n = 0; n < 4; n++)
            #pragma unroll
            for (int r = 0; r < 4; r++) acc[m][n][r] = 0.f;

    auto issue_group = [&](int kf, int stage) {
        int df = (kf - 1) * D;
        uint32_t baseH = sb + (uint32_t)stage * 2u * STAGE_BYTES;
        uint32_t baseL = baseH + STAGE_BYTES;
        #pragma unroll
        for (int pf = 0; pf < 4; pf++) {
            int gf = f0 + pf + df;
            bool fok = (unsigned)gf < F_DIM;
            for (int idx = tid; idx < HW * 8; idx += 256) {
                int tl = idx >> 3, cb = (idx & 7) * 16;
                int gt = t0 - D + tl;
                bool ok = fok && ((unsigned)gt < T_DIM);
                size_t ridx = ok ? ((((size_t)b * F_DIM + gf) * T_DIM + gt) * 64) : 0;
                uint32_t off = (uint32_t)(pf * 48 + tl) * AT_STRIDE + cb;
                cp16(baseH + off, (const unsigned char*)inH + ridx * 2 + cb, ok ? 16 : 0);
                cp16(baseL + off, (const unsigned char*)inL + ridx * 2 + cb, ok ? 16 : 0);
            }
        }
        CP_COMMIT();
    };

    issue_group(0, 0);
    for (int g = 0; g < 3; g++) {
        if (g < 2) { issue_group(g + 1, (g + 1) & 1); CP_WAIT(1); }
        else       { CP_WAIT(0); }
        __syncthreads();

        uint32_t aH = sb + (uint32_t)(g & 1) * 2u * STAGE_BYTES;
        uint32_t aL = aH + STAGE_BYTES;

        for (int kt = 0; kt < 3; kt++) {
            int tap = g * 3 + kt;
            const uint4* wb = reinterpret_cast<const uint4*>(d_wf) + (size_t)(layer * 9 + tap) * 1024;
            uint32_t abase = pfoff + (uint32_t)(kt * D) * AT_STRIDE + laneoff;

            #pragma unroll
            for (int ks = 0; ks < 4; ks++) {
                uint32_t ah[2][4], al[2][4];
                ldmx4(ah[0], aH + abase + ks * 32);
                ldmx4(ah[1], aH + abase + 16 * AT_STRIDE + ks * 32);
                ldmx4(al[0], aL + abase + ks * 32);
                ldmx4(al[1], aL + abase + 16 * AT_STRIDE + ks * 32);

                uint32_t bh[4][2], bl[4][2];
                #pragma unroll
                for (int n = 0; n < 4; n++) {
                    uint4 q = __ldg(&wb[(ks * 8 + n8b + n) * 32 + lid]);
                    bh[n][0] = q.x; bh[n][1] = q.y; bl[n][0] = q.z; bl[n][1] = q.w;
                }
                // split-term outer: 8 independent HMMAs between dependent reuses
                #pragma unroll
                for (int m = 0; m < 2; m++)
                    #pragma unroll
                    for (int n = 0; n < 4; n++) hmma(acc[m][n], ah[m], bh[n]);
                #pragma unroll
                for (int m = 0; m < 2; m++)
                    #pragma unroll
                    for (int n = 0; n < 4; n++) hmma(acc[m][n], ah[m], bl[n]);
                #pragma unroll
                for (int m = 0; m < 2; m++)
                    #pragma unroll
                    for (int n = 0; n < 4; n++) hmma(acc[m][n], al[m], bh[n]);
            }
        }
        __syncthreads();
    }

    // ---- epilogue: bias + leaky + bf16 hi/lo NHWC store ----
    const float* bias = reinterpret_cast<const float*>(smem + SM_BIAS_OFF);
    #pragma unroll
    for (int m = 0; m < 2; m++) {
        #pragma unroll
        for (int r2 = 0; r2 < 2; r2++) {
            int p = mrow0 + m * 16 + (lid >> 2) + r2 * 8;
            int gf = f0 + (p >> 5), gt = t0 + (p & 31);
            if (gf < F_DIM && gt < T_DIM) {
                size_t ridx = (((size_t)b * F_DIM + gf) * T_DIM + gt) * 64;
                #pragma unroll
                for (int n = 0; n < 4; n++) {
                    int oc = ocw + n * 8 + (lid & 3) * 2;
                    float y0 = acc[m][n][r2 * 2 + 0] + bias[oc];
                    float y1 = acc[m][n][r2 * 2 + 1] + bias[oc + 1];
                    y0 = (y0 > 0.f) ? y0 : SLOPE * y0;
                    y1 = (y1 > 0.f) ? y1 : SLOPE * y1;
                    float h0 = __bfloat162float(__float2bfloat16(y0));
                    float h1 = __bfloat162float(__float2bfloat16(y1));
                    *reinterpret_cast<uint32_t*>(outH + ridx + oc) = pack_bf2(h0, h1);
                    *reinterpret_cast<uint32_t*>(outL + ridx + oc) = pack_bf2(y0 - h0, y1 - h1);
                }
            }
        }
    }
}

// ======================= last conv (64 -> 1, 3x3, pad 1) =======================
__global__ __launch_bounds__(256) void last_kernel(float* __restrict__ out) {
    __shared__ float sw[577];
    int tid = threadIdx.x;
    for (int i = tid; i < 577; i += 256) sw[i] = d_wl[i];
    __syncthreads();

    int pid = blockIdx.x * 256 + tid;
    if (pid >= NTOT) return;
    int b = pid / NPIX, rem = pid % NPIX;
    int f = rem / T_DIM, t = rem % T_DIM;

    float acc = sw[576];
    #pragma unroll
    for (int kf = 0; kf < 3; kf++) {
        int fi = f + kf - 1;
        if (fi < 0 || fi >= F_DIM) continue;
        #pragma unroll
        for (int kt = 0; kt < 3; kt++) {
            int ti = t + kt - 1;
            if (ti < 0 || ti >= T_DIM) continue;
            size_t ridx = (((size_t)b * F_DIM + fi) * T_DIM + ti) * 64;
            int wi = kf * 3 + kt;
            #pragma unroll
            for (int c8 = 0; c8 < 8; c8++) {
                uint4 qh = *reinterpret_cast<const uint4*>(d_a0h + ridx + c8 * 8);
                uint4 ql = *reinterpret_cast<const uint4*>(d_a0l + ridx + c8 * 8);
                const uint32_t* ph = &qh.x;
                const uint32_t* pl = &ql.x;
                #pragma unroll
                for (int q = 0; q < 4; q++) {
                    __nv_bfloat162 h2 = *reinterpret_cast<const __nv_bfloat162*>(&ph[q]);
                    __nv_bfloat162 l2 = *reinterpret_cast<const __nv_bfloat162*>(&pl[q]);
                    float2 hf = __bfloat1622float2(h2);
                    float2 lf = __bfloat1622float2(l2);
                    int c = c8 * 8 + q * 2;
                    acc += (hf.x + lf.x) * sw[c * 9 + wi];
                    acc += (hf.y + lf.y) * sw[(c + 1) * 9 + wi];
                }
            }
        }
    }
    out[pid] = acc;
}

// ======================= launch =======================
extern "C" void kernel_launch(void* const* d_in, const int* in_sizes, int n_in,
                              void* d_out, int out_size) {
    const float* x      = (const float*)d_in[0];
    const float* v_h    = (const float*)d_in[1];
    const float* g_h    = (const float*)d_in[2];
    const float* b_h    = (const float*)d_in[3];
    const float* vs     = (const float*)d_in[4];
    const float* gs     = (const float*)d_in[5];
    const float* bs     = (const float*)d_in[6];
    const float* v_last = (const float*)d_in[7];
    const float* g_last = (const float*)d_in[8];
    const float* b_last = (const float*)d_in[9];
    float* out = (float*)d_out;

    cudaFuncSetAttribute(conv3_mma, cudaFuncAttributeMaxDynamicSharedMemorySize, CONV3_SMEM);

    prep_kernel<<<577, 128>>>(v_h, g_h, vs, gs, v_last, g_last, b_last);
    wfrag_kernel<<<dim3(8, 9), 256>>>();
    stft_kernel<<<dim3(257, NB), 256>>>(x);
    conv1_kernel<<<(NTOT + 255) / 256, 256>>>(b_h);

    dim3 cg(9, 65, NB);
    for (int L = 0; L < 8; L++)
        conv3_mma<<<cg, 256, CONV3_SMEM>>>(L, L + 1, bs);

    last_kernel<<<(NTOT + 255) / 256, 256>>>(out);
}

// round 6
// speedup vs baseline: 4.6062x; 1.0421x over previous
#include <cuda_runtime.h>
#include <cuda_bf16.h>
#include <stdint.h>
#include <math.h>

#define F_DIM 257
#define T_DIM 257
#define NB 4
#define NPIX (F_DIM * T_DIM)        // 66049
#define NTOT (NB * NPIX)            // 264196
#define SLOPE 0.2f

// ======================= scratch =======================
__device__ float d_h[NB * 2 * NPIX];                                // STFT (B,2,F,T)
__device__ __align__(16) unsigned short d_a0h[(size_t)NTOT * 64];   // NHWC bf16 hi
__device__ __align__(16) unsigned short d_a0l[(size_t)NTOT * 64];   // NHWC bf16 lo
__device__ __align__(16) unsigned short d_a1h[(size_t)NTOT * 64];
__device__ __align__(16) unsigned short d_a1l[(size_t)NTOT * 64];
__device__ float d_wh[14 * 7 * 64];                                 // conv1 fp32 [ci][kw][o]
__device__ float d_wm[8 * 64 * 9 * 64];                             // mid fp32 [L][(c*9+tap)*64+o]
__device__ __align__(16) uint32_t d_wf[8 * 9 * 4 * 8 * 128];        // B frags [L*9+tap][ks][n8][lane][4]
__device__ float d_wl[578];                                         // last conv fp32

// ======================= small PTX helpers =======================
__device__ __forceinline__ uint32_t smem_u32(const void* p) {
    uint32_t a;
    asm("{ .reg .u64 t; cvta.to.shared.u64 t, %1; cvt.u32.u64 %0, t; }" : "=r"(a) : "l"(p));
    return a;
}
__device__ __forceinline__ void cp16(uint32_t dst, const void* src, int src_bytes) {
    asm volatile("cp.async.cg.shared.global [%0], [%1], 16, %2;"
                 :: "r"(dst), "l"(src), "r"(src_bytes) : "memory");
}
#define CP_COMMIT() asm volatile("cp.async.commit_group;" ::: "memory")
#define CP_WAIT(n)  asm volatile("cp.async.wait_group %0;" :: "n"(n) : "memory")

__device__ __forceinline__ void hmma(float* c, const uint32_t* a, const uint32_t* b) {
    asm volatile(
        "mma.sync.aligned.m16n8k16.row.col.f32.bf16.bf16.f32 "
        "{%0,%1,%2,%3}, {%4,%5,%6,%7}, {%8,%9}, {%0,%1,%2,%3};"
        : "+f"(c[0]), "+f"(c[1]), "+f"(c[2]), "+f"(c[3])
        : "r"(a[0]), "r"(a[1]), "r"(a[2]), "r"(a[3]), "r"(b[0]), "r"(b[1]));
}
__device__ __forceinline__ void ldmx4(uint32_t* r, uint32_t addr) {
    asm volatile("ldmatrix.sync.aligned.m8n8.x4.shared.b16 {%0,%1,%2,%3}, [%4];"
        : "=r"(r[0]), "=r"(r[1]), "=r"(r[2]), "=r"(r[3]) : "r"(addr));
}
__device__ __forceinline__ void stmx4(uint32_t addr, const uint32_t* r) {
    asm volatile("stmatrix.sync.aligned.m8n8.x4.shared.b16 [%0], {%1,%2,%3,%4};"
        :: "r"(addr), "r"(r[0]), "r"(r[1]), "r"(r[2]), "r"(r[3]) : "memory");
}
__device__ __forceinline__ uint32_t pack_bf2(float a, float b) {
    __nv_bfloat162 h = __floats2bfloat162_rn(a, b);
    return *reinterpret_cast<uint32_t*>(&h);
}

// ======================= weight-norm prep =======================
__global__ void prep_kernel(const float* __restrict__ v_h, const float* __restrict__ g_h,
                            const float* __restrict__ vs,  const float* __restrict__ gs,
                            const float* __restrict__ v_last, const float* __restrict__ g_last,
                            const float* __restrict__ b_last) {
    __shared__ float red[128];
    int bid = blockIdx.x, tid = threadIdx.x;
    const float* base; int n; float g; int o = 0;
    if (bid < 64)        { o = bid; base = v_h + o * 98; n = 98; g = g_h[o]; }
    else if (bid < 576)  { int L = (bid - 64) >> 6; o = (bid - 64) & 63;
                           base = vs + (size_t)(L * 64 + o) * 576; n = 576; g = gs[L * 64 + o]; }
    else                 { base = v_last; n = 576; g = g_last[0]; }

    float s = 0.f;
    for (int i = tid; i < n; i += 128) { float v = base[i]; s += v * v; }
    red[tid] = s; __syncthreads();
    for (int k = 64; k > 0; k >>= 1) { if (tid < k) red[tid] += red[tid + k]; __syncthreads(); }
    float scale = g * rsqrtf(red[0]);

    if (bid < 64) {
        for (int i = tid; i < n; i += 128) d_wh[i * 64 + o] = base[i] * scale;
    } else if (bid < 576) {
        int L = (bid - 64) >> 6;
        for (int i = tid; i < n; i += 128) d_wm[(size_t)L * 36864 + i * 64 + o] = base[i] * scale;
    } else {
        for (int i = tid; i < n; i += 128) d_wl[i] = base[i] * scale;
        if (tid == 0) d_wl[576] = b_last[0];
    }
}

// ======================= build B fragments: one uint4 per lane =======================
__global__ void wfrag_kernel() {
    int L = blockIdx.x, tap = blockIdx.y;
    const float* wm = d_wm + (size_t)L * 36864;
    for (int e = threadIdx.x; e < 1024; e += 256) {
        int lane = e & 31, n8 = (e >> 5) & 7, ks = e >> 8;
        int nn = n8 * 8 + (lane >> 2);
        uint32_t w[4];
        #pragma unroll
        for (int r = 0; r < 2; r++) {
            int k0 = ks * 16 + r * 8 + (lane & 3) * 2;
            float w0 = wm[(k0 * 9 + tap) * 64 + nn];
            float w1 = wm[((k0 + 1) * 9 + tap) * 64 + nn];
            __nv_bfloat16 h0 = __float2bfloat16(w0), h1 = __float2bfloat16(w1);
            __nv_bfloat16 l0 = __float2bfloat16(w0 - __bfloat162float(h0));
            __nv_bfloat16 l1 = __float2bfloat16(w1 - __bfloat162float(h1));
            w[r]     = ((uint32_t)__bfloat16_as_ushort(h1) << 16) | __bfloat16_as_ushort(h0);
            w[2 + r] = ((uint32_t)__bfloat16_as_ushort(l1) << 16) | __bfloat16_as_ushort(l0);
        }
        size_t idx = (((size_t)(L * 9 + tap) * 4 + ks) * 8 + n8) * 128 + lane * 4;
        *reinterpret_cast<uint4*>(d_wf + idx) = make_uint4(w[0], w[1], w[2], w[3]);
    }
}

// ======================= STFT =======================
__global__ void stft_kernel(const float* __restrict__ x) {
    __shared__ float s[512], ct[512], st[512];
    int t = blockIdx.x, b = blockIdx.y, tid = threadIdx.x;
    const float* xb = x + (size_t)b * 65536;
    for (int n = tid; n < 512; n += 256) {
        int idx = t * 256 + n - 256;
        if (idx < 0) idx = -idx;
        if (idx >= 65536) idx = 131070 - idx;
        float w = 0.5f - 0.5f * cospif(n * (1.0f / 256.0f));
        s[n] = xb[idx] * w;
        float ss, cc;
        sincospif(n * (1.0f / 256.0f), &ss, &cc);
        ct[n] = cc; st[n] = ss;
    }
    __syncthreads();
    for (int f = tid; f < 257; f += 256) {
        float re = 0.f, im = 0.f;
        int m = 0;
        #pragma unroll 8
        for (int n = 0; n < 512; n++) {
            float v = s[n];
            re += v * ct[m];
            im -= v * st[m];
            m = (m + f) & 511;
        }
        d_h[((size_t)(b * 2 + 0) * F_DIM + f) * T_DIM + t] = re;
        d_h[((size_t)(b * 2 + 1) * F_DIM + f) * T_DIM + t] = im;
    }
}

// ======================= fused lower + conv1 + leaky -> NHWC bf16 hi/lo =======================
// 256 threads = 128 pixels x 2 oc-halves (32 accums/thread for occupancy).
__global__ __launch_bounds__(256) void conv1_kernel(const float* __restrict__ b_h) {
    __shared__ float sw[1792];
    __shared__ float sb[64];
    int tid = threadIdx.x;
    for (int i = tid; i < 1792; i += 256) sw[i] = d_wh[4480 + i];
    if (tid < 64) sb[tid] = b_h[tid];
    __syncthreads();

    int half = tid >> 7, px = tid & 127;
    int pid = blockIdx.x * 128 + px;
    if (pid >= NTOT) return;
    int b = pid / NPIX, rem = pid % NPIX;
    int f = rem / T_DIM, t = rem % T_DIM;

    const float shift5 = 154.15067982725832f;   // 1000*ln(7/6)
    float src  = (float)f - shift5;
    float lof  = floorf(src);
    float frac = src - lof;
    int   il   = (int)lof;
    const float* hb0 = d_h + ((size_t)(b * 2 + 0) * F_DIM) * T_DIM;
    const float* hb1 = d_h + ((size_t)(b * 2 + 1) * F_DIM) * T_DIM;

    float low[4][7];
    #pragma unroll
    for (int kw = 0; kw < 7; kw++) {
        int tt = t + kw - 3;
        bool tv = (tt >= 0) && (tt < T_DIM);
        float a0 = 0.f, a1 = 0.f, c0 = 0.f, c1 = 0.f, i0 = 0.f, i1 = 0.f;
        if (tv) {
            if (il >= 0 && il < F_DIM)          { a0 = hb0[il * T_DIM + tt];        a1 = hb1[il * T_DIM + tt]; }
            if (il + 1 >= 0 && il + 1 < F_DIM)  { c0 = hb0[(il + 1) * T_DIM + tt];  c1 = hb1[(il + 1) * T_DIM + tt]; }
            i0 = hb0[f * T_DIM + tt]; i1 = hb1[f * T_DIM + tt];
        }
        low[0][kw] = (1.0f - frac) * a0 + frac * c0;
        low[1][kw] = (1.0f - frac) * a1 + frac * c1;
        low[2][kw] = i0;
        low[3][kw] = i1;
    }

    float acc[32];
    #pragma unroll
    for (int o = 0; o < 32; o++) acc[o] = sb[half * 32 + o];
    #pragma unroll
    for (int ci = 0; ci < 4; ci++) {
        #pragma unroll
        for (int kw = 0; kw < 7; kw++) {
            float xv = low[ci][kw];
            const float* wp = &sw[(ci * 7 + kw) * 64 + half * 32];
            #pragma unroll
            for (int o = 0; o < 32; o++) acc[o] += xv * wp[o];
        }
    }

    size_t ridx = (size_t)pid * 64 + half * 32;
    #pragma unroll
    for (int c8 = 0; c8 < 4; c8++) {
        float yv[8], hv[8];
        #pragma unroll
        for (int j = 0; j < 8; j++) {
            float y = acc[c8 * 8 + j];
            y = (y > 0.f) ? y : SLOPE * y;
            yv[j] = y;
            hv[j] = __bfloat162float(__float2bfloat16(y));
        }
        uint4 qh, ql;
        qh.x = pack_bf2(hv[0], hv[1]); qh.y = pack_bf2(hv[2], hv[3]);
        qh.z = pack_bf2(hv[4], hv[5]); qh.w = pack_bf2(hv[6], hv[7]);
        ql.x = pack_bf2(yv[0] - hv[0], yv[1] - hv[1]); ql.y = pack_bf2(yv[2] - hv[2], yv[3] - hv[3]);
        ql.z = pack_bf2(yv[4] - hv[4], yv[5] - hv[5]); ql.w = pack_bf2(yv[6] - hv[6], yv[7] - hv[7]);
        *reinterpret_cast<uint4*>(d_a0h + ridx + c8 * 8) = qh;
        *reinterpret_cast<uint4*>(d_a0l + ridx + c8 * 8) = ql;
    }
}

// ======================= dilated 3x3 conv: pipelined halo implicit GEMM =======================
#define AT_STRIDE 144
#define STAGE_BYTES (192 * AT_STRIDE)          // 4 pf rows x 48 t-slots
#define SM_BIAS_OFF (4 * STAGE_BYTES)          // 110592
#define CONV3_SMEM (SM_BIAS_OFF + 256)

__global__ __launch_bounds__(256, 2) void conv3_mma(int layer, int D, const float* __restrict__ bs) {
    extern __shared__ __align__(16) unsigned char smem[];
    uint32_t sb = smem_u32(smem);
    int tid = threadIdx.x, wid = tid >> 5, lid = tid & 31;
    int t0 = blockIdx.x * 32, f0 = blockIdx.y * 4, b = blockIdx.z;
    const int HW = 32 + 2 * D;

    const unsigned short* inH = (layer & 1) ? d_a1h : d_a0h;
    const unsigned short* inL = (layer & 1) ? d_a1l : d_a0l;
    unsigned short* outH = (layer & 1) ? d_a0h : d_a1h;
    unsigned short* outL = (layer & 1) ? d_a0l : d_a1l;

    if (tid < 64) *reinterpret_cast<float*>(smem + SM_BIAS_OFF + tid * 4) = bs[layer * 64 + tid];

    int mrow0 = (wid & 3) * 32;
    int ocw   = (wid >> 2) * 32;
    int n8b   = (wid >> 2) * 4;

    int mat = lid >> 3, rowin = lid & 7;
    uint32_t laneoff = (uint32_t)(((mat & 1) * 8 + rowin) * AT_STRIDE + (mat >> 1) * 16);
    uint32_t pfoff   = (uint32_t)((mrow0 >> 5) * 48 * AT_STRIDE);

    float acc[2][4][4];
    #pragma unroll
    for (int m = 0; m < 2; m++)
        #pragma unroll
        for (int n = 0; n < 4; n++)
            #pragma unroll
            for (int r = 0; r < 4; r++) acc[m][n][r] = 0.f;

    auto issue_group = [&](int kf, int stage) {
        int df = (kf - 1) * D;
        uint32_t baseH = sb + (uint32_t)stage * 2u * STAGE_BYTES;
        uint32_t baseL = baseH + STAGE_BYTES;
        #pragma unroll
        for (int pf = 0; pf < 4; pf++) {
            int gf = f0 + pf + df;
            bool fok = (unsigned)gf < F_DIM;
            for (int idx = tid; idx < HW * 8; idx += 256) {
                int tl = idx >> 3, cb = (idx & 7) * 16;
                int gt = t0 - D + tl;
                bool ok = fok && ((unsigned)gt < T_DIM);
                size_t ridx = ok ? ((((size_t)b * F_DIM + gf) * T_DIM + gt) * 64) : 0;
                uint32_t off = (uint32_t)(pf * 48 + tl) * AT_STRIDE + cb;
                cp16(baseH + off, (const unsigned char*)inH + ridx * 2 + cb, ok ? 16 : 0);
                cp16(baseL + off, (const unsigned char*)inL + ridx * 2 + cb, ok ? 16 : 0);
            }
        }
        CP_COMMIT();
    };

    issue_group(0, 0);
    for (int g = 0; g < 3; g++) {
        if (g < 2) { issue_group(g + 1, (g + 1) & 1); CP_WAIT(1); }
        else       { CP_WAIT(0); }
        __syncthreads();

        uint32_t aH = sb + (uint32_t)(g & 1) * 2u * STAGE_BYTES;
        uint32_t aL = aH + STAGE_BYTES;

        for (int kt = 0; kt < 3; kt++) {
            int tap = g * 3 + kt;
            const uint4* wb = reinterpret_cast<const uint4*>(d_wf) + (size_t)(layer * 9 + tap) * 1024;
            uint32_t abase = pfoff + (uint32_t)(kt * D) * AT_STRIDE + laneoff;

            #pragma unroll
            for (int ks = 0; ks < 4; ks++) {
                uint32_t ah[2][4], al[2][4];
                ldmx4(ah[0], aH + abase + ks * 32);
                ldmx4(ah[1], aH + abase + 16 * AT_STRIDE + ks * 32);
                ldmx4(al[0], aL + abase + ks * 32);
                ldmx4(al[1], aL + abase + 16 * AT_STRIDE + ks * 32);

                uint32_t bh[4][2], bl[4][2];
                #pragma unroll
                for (int n = 0; n < 4; n++) {
                    uint4 q = __ldg(&wb[(ks * 8 + n8b + n) * 32 + lid]);
                    bh[n][0] = q.x; bh[n][1] = q.y; bl[n][0] = q.z; bl[n][1] = q.w;
                }
                #pragma unroll
                for (int m = 0; m < 2; m++)
                    #pragma unroll
                    for (int n = 0; n < 4; n++) hmma(acc[m][n], ah[m], bh[n]);
                #pragma unroll
                for (int m = 0; m < 2; m++)
                    #pragma unroll
                    for (int n = 0; n < 4; n++) hmma(acc[m][n], ah[m], bl[n]);
                #pragma unroll
                for (int m = 0; m < 2; m++)
                    #pragma unroll
                    for (int n = 0; n < 4; n++) hmma(acc[m][n], al[m], bh[n]);
            }
        }
        __syncthreads();
    }

    // ---- epilogue: bias + leaky + hi/lo split, stmatrix staging, coalesced STG.128 ----
    // staging: per-warp 5120B region in the (now dead) stage buffers.
    // rows = 32 pixels at 80B stride (conflict-free stmatrix phases), hi at +0, lo at +2560.
    const float* bias = reinterpret_cast<const float*>(smem + SM_BIAS_OFF);
    uint32_t stg = sb + (uint32_t)wid * 5120u;
    unsigned char* stgp = smem + wid * 5120;

    #pragma unroll
    for (int m = 0; m < 2; m++) {
        uint32_t hreg[2][4], lreg[2][4];   // [r2][n]
        #pragma unroll
        for (int n = 0; n < 4; n++) {
            int oc = ocw + n * 8 + (lid & 3) * 2;
            float b0 = bias[oc], b1 = bias[oc + 1];
            #pragma unroll
            for (int r2 = 0; r2 < 2; r2++) {
                float y0 = acc[m][n][r2 * 2 + 0] + b0;
                float y1 = acc[m][n][r2 * 2 + 1] + b1;
                y0 = (y0 > 0.f) ? y0 : SLOPE * y0;
                y1 = (y1 > 0.f) ? y1 : SLOPE * y1;
                float h0 = __bfloat162float(__float2bfloat16(y0));
                float h1 = __bfloat162float(__float2bfloat16(y1));
                hreg[r2][n] = pack_bf2(h0, h1);
                lreg[r2][n] = pack_bf2(y0 - h0, y1 - h1);
            }
        }
        uint32_t arow = stg + (uint32_t)((m * 16 + rowin) * 80 + mat * 16);
        stmx4(arow,            hreg[0]);
        stmx4(arow + 8 * 80,   hreg[1]);
        stmx4(arow + 2560,     lreg[0]);
        stmx4(arow + 2560 + 8 * 80, lreg[1]);
    }
    __syncwarp();

    int gfx = f0 + (wid & 3);
    if (gfx < F_DIM) {
        #pragma unroll
        for (int it = 0; it < 4; it++) {
            int p = it * 8 + (lid >> 2);
            int gt = t0 + p;
            uint4 vh = *reinterpret_cast<const uint4*>(stgp + p * 80 + (lid & 3) * 16);
            uint4 vl = *reinterpret_cast<const uint4*>(stgp + 2560 + p * 80 + (lid & 3) * 16);
            if (gt < T_DIM) {
                size_t ridx = (((size_t)b * F_DIM + gfx) * T_DIM + gt) * 64 + ocw + (lid & 3) * 8;
                *reinterpret_cast<uint4*>(outH + ridx) = vh;
                *reinterpret_cast<uint4*>(outL + ridx) = vl;
            }
        }
    }
}

// ======================= last conv (64 -> 1, 3x3, pad 1) =======================
__global__ __launch_bounds__(256) void last_kernel(float* __restrict__ out) {
    __shared__ float sw[577];
    int tid = threadIdx.x;
    for (int i = tid; i < 577; i += 256) sw[i] = d_wl[i];
    __syncthreads();

    int pid = blockIdx.x * 256 + tid;
    if (pid >= NTOT) return;
    int b = pid / NPIX, rem = pid % NPIX;
    int f = rem / T_DIM, t = rem % T_DIM;

    float acc = sw[576];
    #pragma unroll
    for (int kf = 0; kf < 3; kf++) {
        int fi = f + kf - 1;
        if (fi < 0 || fi >= F_DIM) continue;
        #pragma unroll
        for (int kt = 0; kt < 3; kt++) {
            int ti = t + kt - 1;
            if (ti < 0 || ti >= T_DIM) continue;
            size_t ridx = (((size_t)b * F_DIM + fi) * T_DIM + ti) * 64;
            int wi = kf * 3 + kt;
            #pragma unroll
            for (int c8 = 0; c8 < 8; c8++) {
                uint4 qh = *reinterpret_cast<const uint4*>(d_a0h + ridx + c8 * 8);
                uint4 ql = *reinterpret_cast<const uint4*>(d_a0l + ridx + c8 * 8);
                const uint32_t* ph = &qh.x;
                const uint32_t* pl = &ql.x;
                #pragma unroll
                for (int q = 0; q < 4; q++) {
                    __nv_bfloat162 h2 = *reinterpret_cast<const __nv_bfloat162*>(&ph[q]);
                    __nv_bfloat162 l2 = *reinterpret_cast<const __nv_bfloat162*>(&pl[q]);
                    float2 hf = __bfloat1622float2(h2);
                    float2 lf = __bfloat1622float2(l2);
                    int c = c8 * 8 + q * 2;
                    acc += (hf.x + lf.x) * sw[c * 9 + wi];
                    acc += (hf.y + lf.y) * sw[(c + 1) * 9 + wi];
                }
            }
        }
    }
    out[pid] = acc;
}

// ======================= launch =======================
extern "C" void kernel_launch(void* const* d_in, const int* in_sizes, int n_in,
                              void* d_out, int out_size) {
    const float* x      = (const float*)d_in[0];
    const float* v_h    = (const float*)d_in[1];
    const float* g_h    = (const float*)d_in[2];
    const float* b_h    = (const float*)d_in[3];
    const float* vs     = (const float*)d_in[4];
    const float* gs     = (const float*)d_in[5];
    const float* bs     = (const float*)d_in[6];
    const float* v_last = (const float*)d_in[7];
    const float* g_last = (const float*)d_in[8];
    const float* b_last = (const float*)d_in[9];
    float* out = (float*)d_out;

    cudaFuncSetAttribute(conv3_mma, cudaFuncAttributeMaxDynamicSharedMemorySize, CONV3_SMEM);

    prep_kernel<<<577, 128>>>(v_h, g_h, vs, gs, v_last, g_last, b_last);
    wfrag_kernel<<<dim3(8, 9), 256>>>();
    stft_kernel<<<dim3(257, NB), 256>>>(x);
    conv1_kernel<<<(NTOT + 127) / 128, 256>>>(b_h);

    dim3 cg(9, 65, NB);
    for (int L = 0; L < 8; L++)
        conv3_mma<<<cg, 256, CONV3_SMEM>>>(L, L + 1, bs);

    last_kernel<<<(NTOT + 255) / 256, 256>>>(out);
}

// round 7
// speedup vs baseline: 4.7727x; 1.0362x over previous
#include <cuda_runtime.h>
#include <cuda_bf16.h>
#include <stdint.h>
#include <math.h>

#define F_DIM 257
#define T_DIM 257
#define NB 4
#define NPIX (F_DIM * T_DIM)        // 66049
#define NTOT (NB * NPIX)            // 264196
#define SLOPE 0.2f

// ======================= scratch =======================
__device__ float d_h[NB * 2 * NPIX];                                // STFT (B,2,F,T)
__device__ __align__(16) unsigned short d_a0h[(size_t)NTOT * 64];   // NHWC bf16 hi
__device__ __align__(16) unsigned short d_a0l[(size_t)NTOT * 64];   // NHWC bf16 lo
__device__ __align__(16) unsigned short d_a1h[(size_t)NTOT * 64];
__device__ __align__(16) unsigned short d_a1l[(size_t)NTOT * 64];
__device__ float d_wh[14 * 7 * 64];                                 // conv1 fp32 [ci][kw][o]
__device__ float d_wm[8 * 64 * 9 * 64];                             // mid fp32 [L][(c*9+tap)*64+o]
__device__ __align__(16) uint32_t d_wf[8 * 9 * 4 * 8 * 128];        // B frags [L*9+tap][ks][n8][lane][4]
__device__ float d_wl[578];                                         // last conv fp32

// ======================= small PTX helpers =======================
__device__ __forceinline__ uint32_t smem_u32(const void* p) {
    uint32_t a;
    asm("{ .reg .u64 t; cvta.to.shared.u64 t, %1; cvt.u32.u64 %0, t; }" : "=r"(a) : "l"(p));
    return a;
}
__device__ __forceinline__ void cp16(uint32_t dst, const void* src, int src_bytes) {
    asm volatile("cp.async.cg.shared.global [%0], [%1], 16, %2;"
                 :: "r"(dst), "l"(src), "r"(src_bytes) : "memory");
}
#define CP_COMMIT() asm volatile("cp.async.commit_group;" ::: "memory")
#define CP_WAIT(n)  asm volatile("cp.async.wait_group %0;" :: "n"(n) : "memory")

__device__ __forceinline__ void hmma(float* c, const uint32_t* a, const uint32_t* b) {
    asm volatile(
        "mma.sync.aligned.m16n8k16.row.col.f32.bf16.bf16.f32 "
        "{%0,%1,%2,%3}, {%4,%5,%6,%7}, {%8,%9}, {%0,%1,%2,%3};"
        : "+f"(c[0]), "+f"(c[1]), "+f"(c[2]), "+f"(c[3])
        : "r"(a[0]), "r"(a[1]), "r"(a[2]), "r"(a[3]), "r"(b[0]), "r"(b[1]));
}
__device__ __forceinline__ void ldmx4(uint32_t* r, uint32_t addr) {
    asm volatile("ldmatrix.sync.aligned.m8n8.x4.shared.b16 {%0,%1,%2,%3}, [%4];"
        : "=r"(r[0]), "=r"(r[1]), "=r"(r[2]), "=r"(r[3]) : "r"(addr));
}
__device__ __forceinline__ void stmx4(uint32_t addr, const uint32_t* r) {
    asm volatile("stmatrix.sync.aligned.m8n8.x4.shared.b16 [%0], {%1,%2,%3,%4};"
        :: "r"(addr), "r"(r[0]), "r"(r[1]), "r"(r[2]), "r"(r[3]) : "memory");
}
__device__ __forceinline__ uint32_t pack_bf2(float a, float b) {
    __nv_bfloat162 h = __floats2bfloat162_rn(a, b);
    return *reinterpret_cast<uint32_t*>(&h);
}

// ======================= weight-norm prep =======================
__global__ void prep_kernel(const float* __restrict__ v_h, const float* __restrict__ g_h,
                            const float* __restrict__ vs,  const float* __restrict__ gs,
                            const float* __restrict__ v_last, const float* __restrict__ g_last,
                            const float* __restrict__ b_last) {
    __shared__ float red[128];
    int bid = blockIdx.x, tid = threadIdx.x;
    const float* base; int n; float g; int o = 0;
    if (bid < 64)        { o = bid; base = v_h + o * 98; n = 98; g = g_h[o]; }
    else if (bid < 576)  { int L = (bid - 64) >> 6; o = (bid - 64) & 63;
                           base = vs + (size_t)(L * 64 + o) * 576; n = 576; g = gs[L * 64 + o]; }
    else                 { base = v_last; n = 576; g = g_last[0]; }

    float s = 0.f;
    for (int i = tid; i < n; i += 128) { float v = base[i]; s += v * v; }
    red[tid] = s; __syncthreads();
    for (int k = 64; k > 0; k >>= 1) { if (tid < k) red[tid] += red[tid + k]; __syncthreads(); }
    float scale = g * rsqrtf(red[0]);

    if (bid < 64) {
        for (int i = tid; i < n; i += 128) d_wh[i * 64 + o] = base[i] * scale;
    } else if (bid < 576) {
        int L = (bid - 64) >> 6;
        for (int i = tid; i < n; i += 128) d_wm[(size_t)L * 36864 + i * 64 + o] = base[i] * scale;
    } else {
        for (int i = tid; i < n; i += 128) d_wl[i] = base[i] * scale;
        if (tid == 0) d_wl[576] = b_last[0];
    }
}

// ======================= build B fragments: one uint4 per lane =======================
__global__ void wfrag_kernel() {
    int L = blockIdx.x, tap = blockIdx.y;
    const float* wm = d_wm + (size_t)L * 36864;
    for (int e = threadIdx.x; e < 1024; e += 256) {
        int lane = e & 31, n8 = (e >> 5) & 7, ks = e >> 8;
        int nn = n8 * 8 + (lane >> 2);
        uint32_t w[4];
        #pragma unroll
        for (int r = 0; r < 2; r++) {
            int k0 = ks * 16 + r * 8 + (lane & 3) * 2;
            float w0 = wm[(k0 * 9 + tap) * 64 + nn];
            float w1 = wm[((k0 + 1) * 9 + tap) * 64 + nn];
            __nv_bfloat16 h0 = __float2bfloat16(w0), h1 = __float2bfloat16(w1);
            __nv_bfloat16 l0 = __float2bfloat16(w0 - __bfloat162float(h0));
            __nv_bfloat16 l1 = __float2bfloat16(w1 - __bfloat162float(h1));
            w[r]     = ((uint32_t)__bfloat16_as_ushort(h1) << 16) | __bfloat16_as_ushort(h0);
            w[2 + r] = ((uint32_t)__bfloat16_as_ushort(l1) << 16) | __bfloat16_as_ushort(l0);
        }
        size_t idx = (((size_t)(L * 9 + tap) * 4 + ks) * 8 + n8) * 128 + lane * 4;
        *reinterpret_cast<uint4*>(d_wf + idx) = make_uint4(w[0], w[1], w[2], w[3]);
    }
}

// ======================= STFT =======================
__global__ void stft_kernel(const float* __restrict__ x) {
    __shared__ float s[512], ct[512], st[512];
    int t = blockIdx.x, b = blockIdx.y, tid = threadIdx.x;
    const float* xb = x + (size_t)b * 65536;
    for (int n = tid; n < 512; n += 256) {
        int idx = t * 256 + n - 256;
        if (idx < 0) idx = -idx;
        if (idx >= 65536) idx = 131070 - idx;
        float w = 0.5f - 0.5f * cospif(n * (1.0f / 256.0f));
        s[n] = xb[idx] * w;
        float ss, cc;
        sincospif(n * (1.0f / 256.0f), &ss, &cc);
        ct[n] = cc; st[n] = ss;
    }
    __syncthreads();
    for (int f = tid; f < 257; f += 256) {
        float re = 0.f, im = 0.f;
        int m = 0;
        #pragma unroll 8
        for (int n = 0; n < 512; n++) {
            float v = s[n];
            re += v * ct[m];
            im -= v * st[m];
            m = (m + f) & 511;
        }
        d_h[((size_t)(b * 2 + 0) * F_DIM + f) * T_DIM + t] = re;
        d_h[((size_t)(b * 2 + 1) * F_DIM + f) * T_DIM + t] = im;
    }
}

// ======================= fused lower + conv1 + leaky (smem row cache) =======================
// One block per (f, b). frac/il uniform per f; interp rows cached in smem.
__global__ __launch_bounds__(288) void conv1_kernel(const float* __restrict__ b_h) {
    __shared__ float rows[4][264];
    __shared__ float sw[1792];
    __shared__ float sb2[64];
    int tid = threadIdx.x;
    int f = blockIdx.x, b = blockIdx.y;
    for (int i = tid; i < 1792; i += 288) sw[i] = d_wh[4480 + i];
    if (tid < 64) sb2[tid] = b_h[tid];

    const float shift5 = 154.15067982725832f;   // 1000*ln(7/6)
    float src  = (float)f - shift5;
    float lof  = floorf(src);
    float frac = src - lof;
    int   il   = (int)lof;
    const float* hb0 = d_h + ((size_t)(b * 2 + 0) * F_DIM) * T_DIM;
    const float* hb1 = d_h + ((size_t)(b * 2 + 1) * F_DIM) * T_DIM;

    for (int j = tid; j < 264; j += 288) {
        int tt = j - 3;
        bool tv = (tt >= 0) && (tt < T_DIM);
        float a0 = 0.f, a1 = 0.f, c0 = 0.f, c1 = 0.f, i0 = 0.f, i1 = 0.f;
        if (tv) {
            if (il >= 0)     { a0 = hb0[il * T_DIM + tt];       a1 = hb1[il * T_DIM + tt]; }
            if (il + 1 >= 0) { c0 = hb0[(il + 1) * T_DIM + tt]; c1 = hb1[(il + 1) * T_DIM + tt]; }
            i0 = hb0[f * T_DIM + tt]; i1 = hb1[f * T_DIM + tt];
        }
        rows[0][j] = (1.0f - frac) * a0 + frac * c0;
        rows[1][j] = (1.0f - frac) * a1 + frac * c1;
        rows[2][j] = i0;
        rows[3][j] = i1;
    }
    __syncthreads();

    int t = tid;
    if (t >= T_DIM) return;

    float low[4][7];
    #pragma unroll
    for (int ci = 0; ci < 4; ci++)
        #pragma unroll
        for (int kw = 0; kw < 7; kw++) low[ci][kw] = rows[ci][t + kw];

    size_t pid = (size_t)b * NPIX + (size_t)f * T_DIM + t;
    #pragma unroll
    for (int half = 0; half < 2; half++) {
        float acc[32];
        #pragma unroll
        for (int o = 0; o < 32; o++) acc[o] = sb2[half * 32 + o];
        #pragma unroll
        for (int ci = 0; ci < 4; ci++)
            #pragma unroll
            for (int kw = 0; kw < 7; kw++) {
                float xv = low[ci][kw];
                const float* wp = &sw[(ci * 7 + kw) * 64 + half * 32];
                #pragma unroll
                for (int o = 0; o < 32; o++) acc[o] += xv * wp[o];
            }
        size_t ridx = pid * 64 + half * 32;
        #pragma unroll
        for (int c8 = 0; c8 < 4; c8++) {
            float yv[8], hv[8];
            #pragma unroll
            for (int j = 0; j < 8; j++) {
                float y = acc[c8 * 8 + j];
                y = (y > 0.f) ? y : SLOPE * y;
                yv[j] = y;
                hv[j] = __bfloat162float(__float2bfloat16(y));
            }
            uint4 qh, ql;
            qh.x = pack_bf2(hv[0], hv[1]); qh.y = pack_bf2(hv[2], hv[3]);
            qh.z = pack_bf2(hv[4], hv[5]); qh.w = pack_bf2(hv[6], hv[7]);
            ql.x = pack_bf2(yv[0] - hv[0], yv[1] - hv[1]); ql.y = pack_bf2(yv[2] - hv[2], yv[3] - hv[3]);
            ql.z = pack_bf2(yv[4] - hv[4], yv[5] - hv[5]); ql.w = pack_bf2(yv[6] - hv[6], yv[7] - hv[7]);
            *reinterpret_cast<uint4*>(d_a0h + ridx + c8 * 8) = qh;
            *reinterpret_cast<uint4*>(d_a0l + ridx + c8 * 8) = ql;
        }
    }
}

// ======================= dilated 3x3 conv: interleaved-load implicit GEMM =======================
// Loads for kf-group g+1 are issued in 1/12 chunks inside the 12 ks-iterations of group g.
#define AT_STRIDE 144
#define STAGE_BYTES (192 * AT_STRIDE)          // 4 pf rows x 48 t-slots
#define SM_BIAS_OFF (4 * STAGE_BYTES)          // 110592
#define CONV3_SMEM (SM_BIAS_OFF + 256)

__global__ __launch_bounds__(256, 2) void conv3_mma(int layer, int D, const float* __restrict__ bs) {
    extern __shared__ __align__(16) unsigned char smem[];
    uint32_t sb = smem_u32(smem);
    int tid = threadIdx.x, wid = tid >> 5, lid = tid & 31;
    int t0 = blockIdx.x * 32, f0 = blockIdx.y * 4, b = blockIdx.z;
    const int HW  = 32 + 2 * D;
    const int HW8 = HW * 8;
    const int E   = 4 * HW8;          // cp16 pairs per group

    const unsigned short* inH = (layer & 1) ? d_a1h : d_a0h;
    const unsigned short* inL = (layer & 1) ? d_a1l : d_a0l;
    unsigned short* outH = (layer & 1) ? d_a0h : d_a1h;
    unsigned short* outL = (layer & 1) ? d_a0l : d_a1l;

    if (tid < 64) *reinterpret_cast<float*>(smem + SM_BIAS_OFF + tid * 4) = bs[layer * 64 + tid];

    int mrow0 = (wid & 3) * 32;
    int ocw   = (wid >> 2) * 32;
    int n8b   = (wid >> 2) * 4;

    int mat = lid >> 3, rowin = lid & 7;
    uint32_t laneoff = (uint32_t)(((mat & 1) * 8 + rowin) * AT_STRIDE + (mat >> 1) * 16);
    uint32_t pfoff   = (uint32_t)((mrow0 >> 5) * 48 * AT_STRIDE);

    float acc[2][4][4];
    #pragma unroll
    for (int m = 0; m < 2; m++)
        #pragma unroll
        for (int n = 0; n < 4; n++)
            #pragma unroll
            for (int r = 0; r < 4; r++) acc[m][n][r] = 0.f;

    // ---- prologue: burst-load group 0 (df = -D) into stage 0 ----
    {
        uint32_t baseH = sb, baseL = sb + STAGE_BYTES;
        for (int e = tid; e < E; e += 256) {
            int pf = (e >= HW8) + (e >= 2 * HW8) + (e >= 3 * HW8);
            int r = e - pf * HW8;
            int tl = r >> 3, cb = (r & 7) * 16;
            int gf = f0 + pf - D, gt = t0 - D + tl;
            bool ok = ((unsigned)gf < F_DIM) && ((unsigned)gt < T_DIM);
            size_t ridx = ok ? ((((size_t)b * F_DIM + gf) * T_DIM + gt) * 64) : 0;
            uint32_t off = (uint32_t)(pf * 48 + tl) * AT_STRIDE + cb;
            cp16(baseH + off, (const unsigned char*)inH + ridx * 2 + cb, ok ? 16 : 0);
            cp16(baseL + off, (const unsigned char*)inL + ridx * 2 + cb, ok ? 16 : 0);
        }
        CP_COMMIT();
    }

    for (int g = 0; g < 3; g++) {
        CP_WAIT(0);
        __syncthreads();

        uint32_t aH = sb + (uint32_t)(g & 1) * 2u * STAGE_BYTES;
        uint32_t aL = aH + STAGE_BYTES;
        uint32_t nH = sb + (uint32_t)((g + 1) & 1) * 2u * STAGE_BYTES;
        uint32_t nL = nH + STAGE_BYTES;
        int dfn = g * D;                         // df for the NEXT group (kf = g+1)

        for (int kt = 0; kt < 3; kt++) {
            int tap = g * 3 + kt;
            const uint4* wb = reinterpret_cast<const uint4*>(d_wf) + (size_t)(layer * 9 + tap) * 1024;
            uint32_t abase = pfoff + (uint32_t)(kt * D) * AT_STRIDE + laneoff;

            #pragma unroll
            for (int ks = 0; ks < 4; ks++) {
                uint32_t ah[2][4], al[2][4];
                ldmx4(ah[0], aH + abase + ks * 32);
                ldmx4(ah[1], aH + abase + 16 * AT_STRIDE + ks * 32);
                ldmx4(al[0], aL + abase + ks * 32);
                ldmx4(al[1], aL + abase + 16 * AT_STRIDE + ks * 32);

                uint32_t bh[4][2], bl[4][2];
                #pragma unroll
                for (int n = 0; n < 4; n++) {
                    uint4 q = __ldg(&wb[(ks * 8 + n8b + n) * 32 + lid]);
                    bh[n][0] = q.x; bh[n][1] = q.y; bl[n][0] = q.z; bl[n][1] = q.w;
                }
                #pragma unroll
                for (int m = 0; m < 2; m++)
                    #pragma unroll
                    for (int n = 0; n < 4; n++) hmma(acc[m][n], ah[m], bh[n]);
                #pragma unroll
                for (int m = 0; m < 2; m++)
                    #pragma unroll
                    for (int n = 0; n < 4; n++) hmma(acc[m][n], ah[m], bl[n]);
                #pragma unroll
                for (int m = 0; m < 2; m++)
                    #pragma unroll
                    for (int n = 0; n < 4; n++) hmma(acc[m][n], al[m], bh[n]);

                // interleaved 1/12 chunk of next group's loads
                if (g < 2) {
                    int e = (kt * 4 + ks) * 256 + tid;
                    if (e < E) {
                        int pf = (e >= HW8) + (e >= 2 * HW8) + (e >= 3 * HW8);
                        int r = e - pf * HW8;
                        int tl = r >> 3, cb = (r & 7) * 16;
                        int gf = f0 + pf + dfn, gt = t0 - D + tl;
                        bool ok = ((unsigned)gf < F_DIM) && ((unsigned)gt < T_DIM);
                        size_t ridx = ok ? ((((size_t)b * F_DIM + gf) * T_DIM + gt) * 64) : 0;
                        uint32_t off = (uint32_t)(pf * 48 + tl) * AT_STRIDE + cb;
                        cp16(nH + off, (const unsigned char*)inH + ridx * 2 + cb, ok ? 16 : 0);
                        cp16(nL + off, (const unsigned char*)inL + ridx * 2 + cb, ok ? 16 : 0);
                    }
                }
                CP_COMMIT();
            }
        }
    }
    __syncthreads();

    // ---- epilogue: bias + leaky + hi/lo split, stmatrix staging, coalesced STG.128 ----
    const float* bias = reinterpret_cast<const float*>(smem + SM_BIAS_OFF);
    uint32_t stg = sb + (uint32_t)wid * 5120u;
    unsigned char* stgp = smem + wid * 5120;

    #pragma unroll
    for (int m = 0; m < 2; m++) {
        uint32_t hreg[2][4], lreg[2][4];
        #pragma unroll
        for (int n = 0; n < 4; n++) {
            int oc = ocw + n * 8 + (lid & 3) * 2;
            float b0 = bias[oc], b1 = bias[oc + 1];
            #pragma unroll
            for (int r2 = 0; r2 < 2; r2++) {
                float y0 = acc[m][n][r2 * 2 + 0] + b0;
                float y1 = acc[m][n][r2 * 2 + 1] + b1;
                y0 = (y0 > 0.f) ? y0 : SLOPE * y0;
                y1 = (y1 > 0.f) ? y1 : SLOPE * y1;
                float h0 = __bfloat162float(__float2bfloat16(y0));
                float h1 = __bfloat162float(__float2bfloat16(y1));
                hreg[r2][n] = pack_bf2(h0, h1);
                lreg[r2][n] = pack_bf2(y0 - h0, y1 - h1);
            }
        }
        uint32_t arow = stg + (uint32_t)((m * 16 + rowin) * 80 + mat * 16);
        stmx4(arow,                 hreg[0]);
        stmx4(arow + 8 * 80,        hreg[1]);
        stmx4(arow + 2560,          lreg[0]);
        stmx4(arow + 2560 + 8 * 80, lreg[1]);
    }
    __syncwarp();

    int gfx = f0 + (wid & 3);
    if (gfx < F_DIM) {
        #pragma unroll
        for (int it = 0; it < 4; it++) {
            int p = it * 8 + (lid >> 2);
            int gt = t0 + p;
            uint4 vh = *reinterpret_cast<const uint4*>(stgp + p * 80 + (lid & 3) * 16);
            uint4 vl = *reinterpret_cast<const uint4*>(stgp + 2560 + p * 80 + (lid & 3) * 16);
            if (gt < T_DIM) {
                size_t ridx = (((size_t)b * F_DIM + gfx) * T_DIM + gt) * 64 + ocw + (lid & 3) * 8;
                *reinterpret_cast<uint4*>(outH + ridx) = vh;
                *reinterpret_cast<uint4*>(outL + ridx) = vl;
            }
        }
    }
}

// ======================= last conv (64 -> 1, 3x3, pad 1): smem-tiled =======================
#define LK_STRIDE 144
#define LK_PX 340                         // 10 f x 34 t halo pixels
#define LK_LO (LK_PX * LK_STRIDE)         // 48960
#define LK_SW (2 * LK_PX * LK_STRIDE)     // 97920
#define LK_SMEM (LK_SW + 2320)

__global__ __launch_bounds__(256, 2) void last_kernel(float* __restrict__ out) {
    extern __shared__ __align__(16) unsigned char lsm[];
    uint32_t sbx = smem_u32(lsm);
    float* sw = reinterpret_cast<float*>(lsm + LK_SW);
    int tid = threadIdx.x;
    int t0 = blockIdx.x * 32, f0 = blockIdx.y * 8, b = blockIdx.z;

    for (int i = tid; i < 577; i += 256) sw[i] = d_wl[i];

    for (int e = tid; e < LK_PX * 8; e += 256) {
        int p = e >> 3, cb = (e & 7) * 16;
        int fl = p / 34, tl = p - fl * 34;
        int gf = f0 - 1 + fl, gt = t0 - 1 + tl;
        bool ok = ((unsigned)gf < F_DIM) && ((unsigned)gt < T_DIM);
        size_t ridx = ok ? ((((size_t)b * F_DIM + gf) * T_DIM + gt) * 64) : 0;
        cp16(sbx + p * LK_STRIDE + cb,        (const unsigned char*)d_a0h + ridx * 2 + cb, ok ? 16 : 0);
        cp16(sbx + LK_LO + p * LK_STRIDE + cb, (const unsigned char*)d_a0l + ridx * 2 + cb, ok ? 16 : 0);
    }
    CP_COMMIT(); CP_WAIT(0);
    __syncthreads();

    int fl = tid >> 5, tl = tid & 31;
    int f = f0 + fl, t = t0 + tl;
    if (f >= F_DIM || t >= T_DIM) return;

    float acc = sw[576];
    #pragma unroll
    for (int kf = 0; kf < 3; kf++) {
        #pragma unroll
        for (int kt = 0; kt < 3; kt++) {
            int p = (fl + kf) * 34 + (tl + kt);
            const unsigned char* hp = lsm + p * LK_STRIDE;
            const unsigned char* lp = lsm + LK_LO + p * LK_STRIDE;
            int wi = kf * 3 + kt;
            #pragma unroll
            for (int c8 = 0; c8 < 8; c8++) {
                uint4 qh = *reinterpret_cast<const uint4*>(hp + c8 * 16);
                uint4 ql = *reinterpret_cast<const uint4*>(lp + c8 * 16);
                const uint32_t* ph = &qh.x;
                const uint32_t* pl = &ql.x;
                #pragma unroll
                for (int q = 0; q < 4; q++) {
                    float2 hf = __bfloat1622float2(*reinterpret_cast<const __nv_bfloat162*>(&ph[q]));
                    float2 lf = __bfloat1622float2(*reinterpret_cast<const __nv_bfloat162*>(&pl[q]));
                    int c = c8 * 8 + q * 2;
                    acc += (hf.x + lf.x) * sw[c * 9 + wi];
                    acc += (hf.y + lf.y) * sw[(c + 1) * 9 + wi];
                }
            }
        }
    }
    out[(size_t)b * NPIX + (size_t)f * T_DIM + t] = acc;
}

// ======================= launch =======================
extern "C" void kernel_launch(void* const* d_in, const int* in_sizes, int n_in,
                              void* d_out, int out_size) {
    const float* x      = (const float*)d_in[0];
    const float* v_h    = (const float*)d_in[1];
    const float* g_h    = (const float*)d_in[2];
    const float* b_h    = (const float*)d_in[3];
    const float* vs     = (const float*)d_in[4];
    const float* gs     = (const float*)d_in[5];
    const float* bs     = (const float*)d_in[6];
    const float* v_last = (const float*)d_in[7];
    const float* g_last = (const float*)d_in[8];
    const float* b_last = (const float*)d_in[9];
    float* out = (float*)d_out;

    cudaFuncSetAttribute(conv3_mma, cudaFuncAttributeMaxDynamicSharedMemorySize, CONV3_SMEM);
    cudaFuncSetAttribute(last_kernel, cudaFuncAttributeMaxDynamicSharedMemorySize, LK_SMEM);

    prep_kernel<<<577, 128>>>(v_h, g_h, vs, gs, v_last, g_last, b_last);
    wfrag_kernel<<<dim3(8, 9), 256>>>();
    stft_kernel<<<dim3(257, NB), 256>>>(x);
    conv1_kernel<<<dim3(257, NB), 288>>>(b_h);

    dim3 cg(9, 65, NB);
    for (int L = 0; L < 8; L++)
        conv3_mma<<<cg, 256, CONV3_SMEM>>>(L, L + 1, bs);

    last_kernel<<<dim3(9, 33, NB), 256, LK_SMEM>>>(out);
}